// round 1
// baseline (speedup 1.0000x reference)
#include <cuda_runtime.h>

// ---------------------------------------------------------------------------
// ConvLSTM block, fp32 baseline.
// x:(4,16,128,128,32) NHWC-ish; W:(3,3,32,256) HWIO; U:(3,3,64,256);
// b:(256); gamma/beta/mm/mv:(64). out:(4,16,64,64,64) fp32.
//
// Stage 1: input conv (stride 2, SAME: pad_lo=0) for all 64 images -> g_xz.
// Stage 2: 16 sequential step kernels: z = conv(h,U,SAME pad 1) + xz_t + b,
//          gates (Keras order i,f,g,o), c/h update, fused BN epilogue.
// h is double-buffered (halo reads cross block boundaries); c updated in place
// (each element owned by exactly one thread).
// ---------------------------------------------------------------------------

#define H2 64
#define W2 64
#define FCH 64
#define CH4 256
#define BATCH 4
#define TSTEPS 16
#define NIMG (BATCH * TSTEPS)

// scratch (static device arrays: allocation-free)
__device__ float g_xz[(size_t)NIMG * H2 * W2 * CH4];      // 268 MB
__device__ float g_h[2][(size_t)BATCH * H2 * W2 * FCH];   // 2 x 4 MB
__device__ float g_c[(size_t)BATCH * H2 * W2 * FCH];      // 4 MB

// ---------------------------------------------------------------------------
// Input conv: (128,128,32) --3x3 s2 SAME--> (64,64,256), per image.
// Block: 8x8 output tile, 256 threads, each thread 4 positions x 16 channels.
// smem: input tile 17*17*32 (36.9KB) + per-tap weight slice 32*256 (32KB).
// ---------------------------------------------------------------------------
#define IC_SIN (17 * 17 * 32)
#define IC_SW  (32 * 256)
#define IC_SMEM ((IC_SIN + IC_SW) * 4)

__global__ __launch_bounds__(256) void input_conv_kernel(
    const float* __restrict__ x, const float* __restrict__ W,
    float* __restrict__ xz)
{
    const int m   = blockIdx.y;                 // image 0..63
    const int oh0 = (blockIdx.x >> 3) * 8;
    const int ow0 = (blockIdx.x & 7) * 8;
    const int ih0 = oh0 * 2, iw0 = ow0 * 2;

    extern __shared__ float smem[];
    float* s_in = smem;            // [r][col][cin], 17x17x32
    float* s_w  = smem + IC_SIN;   // [cin][cout], 32x256

    const int tid = threadIdx.x;

    // load input tile (zero-fill beyond image edge: ih/iw up to 128)
    for (int idx = tid; idx < IC_SIN; idx += 256) {
        int ci  = idx & 31;
        int rc  = idx >> 5;
        int col = rc % 17, r = rc / 17;
        int ih = ih0 + r, iw = iw0 + col;
        float v = 0.f;
        if (ih < 128 && iw < 128)
            v = x[((m * 128 + ih) * 128 + iw) * 32 + ci];
        s_in[idx] = v;
    }

    const int pg = tid >> 4;       // position group 0..15 (4 positions each)
    const int cg = tid & 15;       // channel group 0..15 (16 channels each)
    const int pos0 = pg * 4;

    int ohl[4], owl[4];
#pragma unroll
    for (int k = 0; k < 4; k++) { ohl[k] = (pos0 + k) >> 3; owl[k] = (pos0 + k) & 7; }

    float acc[4][16];
#pragma unroll
    for (int k = 0; k < 4; k++)
#pragma unroll
        for (int j = 0; j < 16; j++) acc[k][j] = 0.f;

    for (int tap = 0; tap < 9; tap++) {
        __syncthreads();
        for (int idx = tid; idx < IC_SW; idx += 256)
            s_w[idx] = W[tap * IC_SW + idx];
        __syncthreads();

        const int kh = tap / 3, kw = tap - kh * 3;
        int ibase[4];
#pragma unroll
        for (int k = 0; k < 4; k++)
            ibase[k] = ((ohl[k] * 2 + kh) * 17 + (owl[k] * 2 + kw)) * 32;

        const float4* w4 = (const float4*)(s_w + cg * 16);
        for (int ci = 0; ci < 32; ci++) {
            float4 wa = w4[ci * 64 + 0];
            float4 wb = w4[ci * 64 + 1];
            float4 wc = w4[ci * 64 + 2];
            float4 wd = w4[ci * 64 + 3];
            float w[16] = {wa.x, wa.y, wa.z, wa.w, wb.x, wb.y, wb.z, wb.w,
                           wc.x, wc.y, wc.z, wc.w, wd.x, wd.y, wd.z, wd.w};
#pragma unroll
            for (int k = 0; k < 4; k++) {
                float a = s_in[ibase[k] + ci];
#pragma unroll
                for (int j = 0; j < 16; j++) acc[k][j] += a * w[j];
            }
        }
    }

#pragma unroll
    for (int k = 0; k < 4; k++) {
        int oh = oh0 + ohl[k], ow = ow0 + owl[k];
        float4* dst = (float4*)(xz + (((size_t)m * H2 + oh) * W2 + ow) * CH4 + cg * 16);
        dst[0] = make_float4(acc[k][0],  acc[k][1],  acc[k][2],  acc[k][3]);
        dst[1] = make_float4(acc[k][4],  acc[k][5],  acc[k][6],  acc[k][7]);
        dst[2] = make_float4(acc[k][8],  acc[k][9],  acc[k][10], acc[k][11]);
        dst[3] = make_float4(acc[k][12], acc[k][13], acc[k][14], acc[k][15]);
    }
}

// ---------------------------------------------------------------------------
// One LSTM step: z = conv(h_in, U, s1 SAME) + xz[:,t] + b; gates; BN output.
// Block: 8x8 spatial tile, one batch, all 256 channels.
// smem: h tile 10x10x64 (25.6KB) + weight slice 64x256 (64KB, reused for z).
// ---------------------------------------------------------------------------
#define ST_SH (10 * 10 * 64)
#define ST_SW (64 * 256)
#define ST_SMEM ((ST_SH + ST_SW) * 4)

__global__ __launch_bounds__(256) void lstm_step_kernel(
    const float* __restrict__ hin, float* __restrict__ hout,
    float* __restrict__ cbuf, const float* __restrict__ xz,
    const float* __restrict__ U, const float* __restrict__ bias,
    const float* __restrict__ gamma, const float* __restrict__ beta,
    const float* __restrict__ mmean, const float* __restrict__ mvar,
    float* __restrict__ out, int t)
{
    const int bb  = blockIdx.y;                 // batch
    const int oh0 = (blockIdx.x >> 3) * 8;
    const int ow0 = (blockIdx.x & 7) * 8;

    extern __shared__ float smem[];
    float* s_h = smem;           // [r][col][cin], 10x10x64
    float* s_w = smem + ST_SH;   // [cin][cout] 64x256; later reused as z [pos][ch]

    const int tid = threadIdx.x;

    // load halo'd h tile (pad 1, zero outside)
    for (int idx = tid; idx < ST_SH; idx += 256) {
        int ci  = idx & 63;
        int rc  = idx >> 6;
        int col = rc % 10, r = rc / 10;
        int ih = oh0 - 1 + r, iw = ow0 - 1 + col;
        float v = 0.f;
        if (ih >= 0 && ih < H2 && iw >= 0 && iw < W2)
            v = hin[((bb * H2 + ih) * W2 + iw) * FCH + ci];
        s_h[idx] = v;
    }

    const int pg = tid >> 4, cg = tid & 15;
    const int pos0 = pg * 4;
    int ohl[4], owl[4];
#pragma unroll
    for (int k = 0; k < 4; k++) { ohl[k] = (pos0 + k) >> 3; owl[k] = (pos0 + k) & 7; }

    float acc[4][16];
#pragma unroll
    for (int k = 0; k < 4; k++)
#pragma unroll
        for (int j = 0; j < 16; j++) acc[k][j] = 0.f;

    for (int tap = 0; tap < 9; tap++) {
        __syncthreads();
        for (int idx = tid; idx < ST_SW; idx += 256)
            s_w[idx] = U[tap * ST_SW + idx];
        __syncthreads();

        const int kh = tap / 3, kw = tap - kh * 3;
        int ibase[4];
#pragma unroll
        for (int k = 0; k < 4; k++)
            ibase[k] = ((ohl[k] + kh) * 10 + (owl[k] + kw)) * 64;

        const float4* w4 = (const float4*)(s_w + cg * 16);
        for (int ci = 0; ci < 64; ci++) {
            float4 wa = w4[ci * 64 + 0];
            float4 wb = w4[ci * 64 + 1];
            float4 wc = w4[ci * 64 + 2];
            float4 wd = w4[ci * 64 + 3];
            float w[16] = {wa.x, wa.y, wa.z, wa.w, wb.x, wb.y, wb.z, wb.w,
                           wc.x, wc.y, wc.z, wc.w, wd.x, wd.y, wd.z, wd.w};
#pragma unroll
            for (int k = 0; k < 4; k++) {
                float a = s_h[ibase[k] + ci];
#pragma unroll
                for (int j = 0; j < 16; j++) acc[k][j] += a * w[j];
            }
        }
    }

    __syncthreads();  // all taps' reads of s_w done; safe to reuse as z stage

    // z = acc + xz + b -> smem
    const float4 b0 = ((const float4*)(bias + cg * 16))[0];
    const float4 b1 = ((const float4*)(bias + cg * 16))[1];
    const float4 b2 = ((const float4*)(bias + cg * 16))[2];
    const float4 b3 = ((const float4*)(bias + cg * 16))[3];
    const int mimg = bb * TSTEPS + t;
#pragma unroll
    for (int k = 0; k < 4; k++) {
        int oh = oh0 + ohl[k], ow = ow0 + owl[k];
        const float4* xp = (const float4*)(xz + (((size_t)mimg * H2 + oh) * W2 + ow) * CH4 + cg * 16);
        float4 x0 = xp[0], x1 = xp[1], x2 = xp[2], x3 = xp[3];
        float* zd = s_w + (pos0 + k) * 256 + cg * 16;
        zd[0]  = acc[k][0]  + x0.x + b0.x;  zd[1]  = acc[k][1]  + x0.y + b0.y;
        zd[2]  = acc[k][2]  + x0.z + b0.z;  zd[3]  = acc[k][3]  + x0.w + b0.w;
        zd[4]  = acc[k][4]  + x1.x + b1.x;  zd[5]  = acc[k][5]  + x1.y + b1.y;
        zd[6]  = acc[k][6]  + x1.z + b1.z;  zd[7]  = acc[k][7]  + x1.w + b1.w;
        zd[8]  = acc[k][8]  + x2.x + b2.x;  zd[9]  = acc[k][9]  + x2.y + b2.y;
        zd[10] = acc[k][10] + x2.z + b2.z;  zd[11] = acc[k][11] + x2.w + b2.w;
        zd[12] = acc[k][12] + x3.x + b3.x;  zd[13] = acc[k][13] + x3.y + b3.y;
        zd[14] = acc[k][14] + x3.z + b3.z;  zd[15] = acc[k][15] + x3.w + b3.w;
    }
    __syncthreads();

    // gates + state update + BN epilogue. 64 pos * 64 fc = 4096 items.
#pragma unroll 4
    for (int q = 0; q < 16; q++) {
        int idx = q * 256 + tid;
        int pos = idx >> 6, fc = idx & 63;
        int oh = oh0 + (pos >> 3), ow = ow0 + (pos & 7);

        float zi = s_w[pos * 256 + fc];
        float zf = s_w[pos * 256 + 64 + fc];
        float zg = s_w[pos * 256 + 128 + fc];
        float zo = s_w[pos * 256 + 192 + fc];

        float gi = fminf(fmaxf(0.2f * zi + 0.5f, 0.f), 1.f);
        float gf = fminf(fmaxf(0.2f * zf + 0.5f, 0.f), 1.f);
        float go = fminf(fmaxf(0.2f * zo + 0.5f, 0.f), 1.f);

        int cidx = ((bb * H2 + oh) * W2 + ow) * FCH + fc;
        float cold = cbuf[cidx];
        float cn = gf * cold + gi * tanhf(zg);
        float hn = go * tanhf(cn);
        cbuf[cidx] = cn;
        hout[cidx] = hn;

        float scale = gamma[fc] * rsqrtf(mvar[fc] + 1e-3f);
        out[((((size_t)bb * TSTEPS + t) * H2 + oh) * W2 + ow) * FCH + fc]
            = (hn - mmean[fc]) * scale + beta[fc];
    }
}

// ---------------------------------------------------------------------------
extern "C" void kernel_launch(void* const* d_in, const int* in_sizes, int n_in,
                              void* d_out, int out_size)
{
    const float* x     = (const float*)d_in[0];
    const float* W     = (const float*)d_in[1];
    const float* U     = (const float*)d_in[2];
    const float* b     = (const float*)d_in[3];
    const float* gamma = (const float*)d_in[4];
    const float* beta  = (const float*)d_in[5];
    const float* mm    = (const float*)d_in[6];
    const float* mv    = (const float*)d_in[7];
    float* out = (float*)d_out;

    float *xz, *hbuf, *cbuf;
    cudaGetSymbolAddress((void**)&xz,   g_xz);
    cudaGetSymbolAddress((void**)&hbuf, g_h);
    cudaGetSymbolAddress((void**)&cbuf, g_c);
    const size_t hsz = (size_t)BATCH * H2 * W2 * FCH;
    float* h0 = hbuf;
    float* h1 = hbuf + hsz;

    cudaFuncSetAttribute(input_conv_kernel,
                         cudaFuncAttributeMaxDynamicSharedMemorySize, IC_SMEM);
    cudaFuncSetAttribute(lstm_step_kernel,
                         cudaFuncAttributeMaxDynamicSharedMemorySize, ST_SMEM);

    // fresh recurrent state every launch (graph-replay safe)
    cudaMemsetAsync(h0, 0, hsz * sizeof(float));
    cudaMemsetAsync(cbuf, 0, hsz * sizeof(float));

    input_conv_kernel<<<dim3(64, NIMG), 256, IC_SMEM>>>(x, W, xz);

    for (int t = 0; t < TSTEPS; t++) {
        const float* hin = (t & 1) ? h1 : h0;
        float*       hout = (t & 1) ? h0 : h1;
        lstm_step_kernel<<<dim3(64, BATCH), 256, ST_SMEM>>>(
            hin, hout, cbuf, xz, U, b, gamma, beta, mm, mv, out, t);
    }
}

// round 2
// speedup vs baseline: 1.7247x; 1.7247x over previous
#include <cuda_runtime.h>

// ---------------------------------------------------------------------------
// ConvLSTM block, fp32, round 2: warp-broadcast weights + conflict-free smem.
// x:(4,16,128,128,32); W:(3,3,32,256); U:(3,3,64,256); b:(256); BN params (64).
// out:(4,16,64,64,64) fp32.
// ---------------------------------------------------------------------------

#define H2 64
#define W2 64
#define FCH 64
#define CH4 256
#define BATCH 4
#define TSTEPS 16
#define NIMG (BATCH * TSTEPS)

__device__ float g_xz[(size_t)NIMG * H2 * W2 * CH4];      // 268 MB
__device__ float g_h[2][(size_t)BATCH * H2 * W2 * FCH];   // 2 x 4 MB
__device__ float g_c[(size_t)BATCH * H2 * W2 * FCH];      // 4 MB

// ===========================================================================
// Input conv: (128,128,32) --3x3 s2 SAME(pad_lo=0)--> (64,64,256) per image.
// 1024 threads = 16 channel-groups x 64 positions (8x8 tile). Warp = one cg
// x 32 positions -> weight LDS broadcasts, conflict-free activation LDS.
// smem: input tile split into even/odd column planes [ci][row*12+half],
// plane stride 205 (odd -> conflict-free fill), + 32x256 weight slice.
// ===========================================================================
#define IC_PLANE 205                    // per-ci plane stride (17 rows x 12)
#define IC_SE 0
#define IC_SO (32 * IC_PLANE)           // 6560
#define IC_SWOFF (2 * 32 * IC_PLANE)    // 13120
#define IC_SMEM ((IC_SWOFF + 32 * 256) * 4)   // 85248 B

__global__ __launch_bounds__(1024, 1) void input_conv_kernel(
    const float* __restrict__ x, const float* __restrict__ W,
    float* __restrict__ xz)
{
    const int m   = blockIdx.y;                 // image 0..63
    const int oh0 = (blockIdx.x >> 3) * 8;
    const int ow0 = (blockIdx.x & 7) * 8;
    const int ih0 = oh0 * 2, iw0 = ow0 * 2;

    extern __shared__ float smem[];
    float* s_e = smem + IC_SE;
    float* s_o = smem + IC_SO;
    float* s_w = smem + IC_SWOFF;       // [cin][cout] 32x256

    const int tid = threadIdx.x;
    const int pos = tid & 63;
    const int cg  = tid >> 6;
    const int r   = pos >> 3;
    const int c   = pos & 7;

    // fill input tile (17x17x32), deinterleaved even/odd columns
    for (int idx = tid; idx < 17 * 17 * 32; idx += 1024) {
        int ci  = idx & 31;
        int rc  = idx >> 5;
        int col = rc % 17, row = rc / 17;
        int ih = ih0 + row, iw = iw0 + col;
        float v = 0.f;
        if (ih < 128 && iw < 128)
            v = x[((m * 128 + ih) * 128 + iw) * 32 + ci];
        float* base = (col & 1) ? s_o : s_e;
        base[ci * IC_PLANE + row * 12 + (col >> 1)] = v;
    }

    float acc[16];
#pragma unroll
    for (int j = 0; j < 16; j++) acc[j] = 0.f;

    for (int tap = 0; tap < 9; tap++) {
        __syncthreads();
        {   // stage weight slice: 8192 floats = 2048 float4
            const float4* src = (const float4*)(W + tap * 32 * 256);
            float4* dst = (float4*)s_w;
            dst[tid] = src[tid];
            dst[tid + 1024] = src[tid + 1024];
        }
        __syncthreads();

        const int kh = tap / 3, kw = tap - kh * 3;
        const float* abase = ((kw & 1) ? s_o : s_e);
        const int aoff = (2 * r + kh) * 12 + c + (kw >> 1);
        const float4* wv = (const float4*)(s_w + cg * 16);

#pragma unroll 4
        for (int ci = 0; ci < 32; ci++) {
            float a = abase[ci * IC_PLANE + aoff];
            float4 w0 = wv[ci * 64 + 0];
            float4 w1 = wv[ci * 64 + 1];
            float4 w2 = wv[ci * 64 + 2];
            float4 w3 = wv[ci * 64 + 3];
            acc[0]  += a * w0.x; acc[1]  += a * w0.y;
            acc[2]  += a * w0.z; acc[3]  += a * w0.w;
            acc[4]  += a * w1.x; acc[5]  += a * w1.y;
            acc[6]  += a * w1.z; acc[7]  += a * w1.w;
            acc[8]  += a * w2.x; acc[9]  += a * w2.y;
            acc[10] += a * w2.z; acc[11] += a * w2.w;
            acc[12] += a * w3.x; acc[13] += a * w3.y;
            acc[14] += a * w3.z; acc[15] += a * w3.w;
        }
    }

    const int oh = oh0 + r, ow = ow0 + c;
    float4* dst = (float4*)(xz + (((size_t)m * H2 + oh) * W2 + ow) * CH4 + cg * 16);
    dst[0] = make_float4(acc[0],  acc[1],  acc[2],  acc[3]);
    dst[1] = make_float4(acc[4],  acc[5],  acc[6],  acc[7]);
    dst[2] = make_float4(acc[8],  acc[9],  acc[10], acc[11]);
    dst[3] = make_float4(acc[12], acc[13], acc[14], acc[15]);
}

// ===========================================================================
// LSTM step: z = conv(h,U,s1 SAME pad1) (+ xz + b in gate pass); gates; BN.
// 1024 threads = 16 cg x 64 pos. smem: s_h [ci][r*40+c] plane stride 401
// (conflict-free fill + a-loads), weight/z union region.
// ===========================================================================
#define ST_HPLANE 401
#define ST_SH (64 * ST_HPLANE)          // 25664 floats
#define ST_WZ 16640                     // max(64*256 weights, 256*65 z)
#define ST_SMEM ((ST_SH + ST_WZ) * 4)   // 169216 B

__global__ __launch_bounds__(1024, 1) void lstm_step_kernel(
    const float* __restrict__ hin, float* __restrict__ hout,
    float* __restrict__ cbuf, const float* __restrict__ xz,
    const float* __restrict__ U, const float* __restrict__ bias,
    const float* __restrict__ gamma, const float* __restrict__ beta,
    const float* __restrict__ mmean, const float* __restrict__ mvar,
    float* __restrict__ out, int t)
{
    const int bb  = blockIdx.y;
    const int oh0 = (blockIdx.x >> 3) * 8;
    const int ow0 = (blockIdx.x & 7) * 8;

    extern __shared__ float smem[];
    float* s_h  = smem;                 // [ci][10x10 padded]
    float* s_wz = smem + ST_SH;         // weights [cin][cout] / later z [ch][65]

    const int tid = threadIdx.x;
    const int pos = tid & 63;
    const int cg  = tid >> 6;
    const int r   = pos >> 3;
    const int c   = pos & 7;

    // fill halo'd h tile (10x10x64), transposed to [ci][spatial]
    for (int idx = tid; idx < 10 * 10 * 64; idx += 1024) {
        int ci  = idx & 63;
        int rc  = idx >> 6;
        int col = rc % 10, row = rc / 10;
        int ih = oh0 - 1 + row, iw = ow0 - 1 + col;
        float v = 0.f;
        if (ih >= 0 && ih < H2 && iw >= 0 && iw < W2)
            v = hin[((bb * H2 + ih) * W2 + iw) * FCH + ci];
        s_h[ci * ST_HPLANE + row * 40 + col] = v;
    }

    float acc[16];
#pragma unroll
    for (int j = 0; j < 16; j++) acc[j] = 0.f;

    for (int tap = 0; tap < 9; tap++) {
        __syncthreads();
        {   // stage weight slice: 16384 floats = 4096 float4
            const float4* src = (const float4*)(U + tap * 64 * 256);
            float4* dst = (float4*)s_wz;
#pragma unroll
            for (int k = 0; k < 4; k++)
                dst[tid + k * 1024] = src[tid + k * 1024];
        }
        __syncthreads();

        const int kh = tap / 3, kw = tap - kh * 3;
        const int aoff = (r + kh) * 40 + c + kw;
        const float4* wv = (const float4*)(s_wz + cg * 16);

#pragma unroll 4
        for (int ci = 0; ci < 64; ci++) {
            float a = s_h[ci * ST_HPLANE + aoff];
            float4 w0 = wv[ci * 64 + 0];
            float4 w1 = wv[ci * 64 + 1];
            float4 w2 = wv[ci * 64 + 2];
            float4 w3 = wv[ci * 64 + 3];
            acc[0]  += a * w0.x; acc[1]  += a * w0.y;
            acc[2]  += a * w0.z; acc[3]  += a * w0.w;
            acc[4]  += a * w1.x; acc[5]  += a * w1.y;
            acc[6]  += a * w1.z; acc[7]  += a * w1.w;
            acc[8]  += a * w2.x; acc[9]  += a * w2.y;
            acc[10] += a * w2.z; acc[11] += a * w2.w;
            acc[12] += a * w3.x; acc[13] += a * w3.y;
            acc[14] += a * w3.z; acc[15] += a * w3.w;
        }
    }

    __syncthreads();   // weights fully consumed; reuse region as z [ch][65]
#pragma unroll
    for (int j = 0; j < 16; j++)
        s_wz[(cg * 16 + j) * 65 + pos] = acc[j];
    __syncthreads();

    // gate pass: 4096 items = 64 pos x 64 fc; lanes vary fc -> coalesced gmem,
    // conflict-free z reads (stride 65).
    const int mimg = bb * TSTEPS + t;
#pragma unroll
    for (int q = 0; q < 4; q++) {
        int idx = q * 1024 + tid;
        int fc  = idx & 63;
        int p   = idx >> 6;
        int oh = oh0 + (p >> 3), ow = ow0 + (p & 7);

        float zi = s_wz[(fc)       * 65 + p];
        float zf = s_wz[(64 + fc)  * 65 + p];
        float zg = s_wz[(128 + fc) * 65 + p];
        float zo = s_wz[(192 + fc) * 65 + p];

        const float* xp = xz + (((size_t)mimg * H2 + oh) * W2 + ow) * CH4 + fc;
        zi += xp[0]   + bias[fc];
        zf += xp[64]  + bias[64 + fc];
        zg += xp[128] + bias[128 + fc];
        zo += xp[192] + bias[192 + fc];

        float gi = fminf(fmaxf(0.2f * zi + 0.5f, 0.f), 1.f);
        float gf = fminf(fmaxf(0.2f * zf + 0.5f, 0.f), 1.f);
        float go = fminf(fmaxf(0.2f * zo + 0.5f, 0.f), 1.f);

        int cidx = ((bb * H2 + oh) * W2 + ow) * FCH + fc;
        float cold = cbuf[cidx];
        float cn = gf * cold + gi * tanhf(zg);
        float hn = go * tanhf(cn);
        cbuf[cidx] = cn;
        hout[cidx] = hn;

        float scale = gamma[fc] * rsqrtf(mvar[fc] + 1e-3f);
        out[((((size_t)bb * TSTEPS + t) * H2 + oh) * W2 + ow) * FCH + fc]
            = (hn - mmean[fc]) * scale + beta[fc];
    }
}

// ---------------------------------------------------------------------------
extern "C" void kernel_launch(void* const* d_in, const int* in_sizes, int n_in,
                              void* d_out, int out_size)
{
    const float* x     = (const float*)d_in[0];
    const float* W     = (const float*)d_in[1];
    const float* U     = (const float*)d_in[2];
    const float* b     = (const float*)d_in[3];
    const float* gamma = (const float*)d_in[4];
    const float* beta  = (const float*)d_in[5];
    const float* mm    = (const float*)d_in[6];
    const float* mv    = (const float*)d_in[7];
    float* out = (float*)d_out;

    float *xz, *hbuf, *cbuf;
    cudaGetSymbolAddress((void**)&xz,   g_xz);
    cudaGetSymbolAddress((void**)&hbuf, g_h);
    cudaGetSymbolAddress((void**)&cbuf, g_c);
    const size_t hsz = (size_t)BATCH * H2 * W2 * FCH;
    float* h0 = hbuf;
    float* h1 = hbuf + hsz;

    cudaFuncSetAttribute(input_conv_kernel,
                         cudaFuncAttributeMaxDynamicSharedMemorySize, IC_SMEM);
    cudaFuncSetAttribute(lstm_step_kernel,
                         cudaFuncAttributeMaxDynamicSharedMemorySize, ST_SMEM);

    cudaMemsetAsync(h0, 0, hsz * sizeof(float));
    cudaMemsetAsync(cbuf, 0, hsz * sizeof(float));

    input_conv_kernel<<<dim3(64, NIMG), 1024, IC_SMEM>>>(x, W, xz);

    for (int t = 0; t < TSTEPS; t++) {
        const float* hin  = (t & 1) ? h1 : h0;
        float*       hout = (t & 1) ? h0 : h1;
        lstm_step_kernel<<<dim3(64, BATCH), 1024, ST_SMEM>>>(
            hin, hout, cbuf, xz, U, b, gamma, beta, mm, mv, out, t);
    }
}

// round 3
// speedup vs baseline: 2.8805x; 1.6701x over previous
#include <cuda_runtime.h>

// ---------------------------------------------------------------------------
// ConvLSTM block, fp32 via packed fma.rn.f32x2 (FFMA2). Round 3.
// x:(4,16,128,128,32); W:(3,3,32,256); U:(3,3,64,256); b:(256); BN(64).
// out:(4,16,64,64,64) fp32.
// xz scratch uses gate-grouped layout [img][cg16][oh][ow][g*4+j], bias folded.
// ---------------------------------------------------------------------------

#define H2 64
#define W2 64
#define FCH 64
#define BATCH 4
#define TSTEPS 16
#define NIMG 64

__device__ float g_xz[(size_t)NIMG * 16 * H2 * W2 * 16];   // 268 MB
__device__ float g_h[2][(size_t)BATCH * H2 * W2 * FCH];    // 2 x 4 MB
__device__ float g_c[(size_t)BATCH * H2 * W2 * FCH];       // 4 MB

// ---- packed fp32 helpers ---------------------------------------------------
#define FMA2(d, a, b) \
    asm("fma.rn.f32x2 %0, %1, %2, %0;" : "+l"(d) : "l"(a), "l"(b))

__device__ __forceinline__ unsigned long long splat2(float x) {
    unsigned r = __float_as_uint(x);
    unsigned long long d;
    asm("mov.b64 %0, {%1, %2};" : "=l"(d) : "r"(r), "r"(r));
    return d;
}
__device__ __forceinline__ float2 unpack2(unsigned long long v) {
    float2 f;
    asm("mov.b64 {%0, %1}, %2;" : "=f"(f.x), "=f"(f.y) : "l"(v));
    return f;
}
__device__ __forceinline__ void cp16(unsigned dst, const float* src) {
    asm volatile("cp.async.cg.shared.global [%0], [%1], 16;"
                 :: "r"(dst), "l"(src));
}
__device__ __forceinline__ void cp_commit() {
    asm volatile("cp.async.commit_group;");
}
__device__ __forceinline__ void cp_wait0() {
    asm volatile("cp.async.wait_group 0;" ::: "memory");
}
__device__ __forceinline__ float hsig(float z) {
    return fminf(fmaxf(0.2f * z + 0.5f, 0.f), 1.f);
}

// ===========================================================================
// Input conv: (128,128,32) --3x3 s2 SAME(pad_lo=0)--> (64,64,256) per image.
// 512 thr = 16 cg x 32 pp; tile 8x16 out; 4 positions x 16 couts per thread.
// s_in single plane [ci][ih*36+iw] (17x33), PLANE=613. Weights staged/tap.
// ===========================================================================
#define IC_RS 36
#define IC_PLANE 613
#define IC_SIN (32 * IC_PLANE)               // 19616 floats
#define IC_SMEM ((IC_SIN + 32 * 256) * 4)    // 111232 B

__global__ __launch_bounds__(512, 1) void input_conv_kernel(
    const float* __restrict__ x, const float* __restrict__ W,
    const float* __restrict__ bias, float* __restrict__ xz)
{
    const int m    = blockIdx.y;                // image 0..63
    const int oh0  = (blockIdx.x >> 2) * 8;
    const int ow0  = (blockIdx.x & 3) * 16;
    const int ih0  = oh0 * 2, iw0 = ow0 * 2;

    extern __shared__ float smem[];
    float* s_in = smem;
    float* s_w  = smem + IC_SIN;

    const int tid = threadIdx.x;
    const int cg  = tid >> 5;
    const int pp  = tid & 31;
    const int c   = pp & 15;
    const int r0  = pp >> 4;

    // fill input tile 17x33x32 (col-fastest -> conflict-free STS)
    for (int idx = tid; idx < 17 * 33 * 32; idx += 512) {
        int ci  = idx / 561;
        int sp  = idx - ci * 561;
        int row = sp / 33, col = sp - row * 33;
        int ih = ih0 + row, iw = iw0 + col;
        float v = 0.f;
        if (ih < 128 && iw < 128)
            v = x[((m * 128 + ih) * 128 + iw) * 32 + ci];
        s_in[ci * IC_PLANE + row * IC_RS + col] = v;
    }

    // stage tap-0 weights: 8192 floats = 2048 x 16B, 4 per thread
    unsigned swu = (unsigned)__cvta_generic_to_shared(s_w);
#pragma unroll
    for (int k = 0; k < 4; k++)
        cp16(swu + (unsigned)(tid + k * 512) * 16, W + (tid + k * 512) * 4);
    cp_commit();

    unsigned long long acc[4][4][2];
#pragma unroll
    for (int k = 0; k < 4; k++)
#pragma unroll
        for (int g = 0; g < 4; g++) { acc[k][g][0] = 0ull; acc[k][g][1] = 0ull; }

    for (int tap = 0; tap < 9; tap++) {
        cp_wait0();
        __syncthreads();

        const int kh = tap / 3, kw = tap - kh * 3;
        const float* ap = s_in + (2 * r0 + kh) * IC_RS + 2 * c + kw;
        const float* wp0 = s_w + 4 * cg;

#pragma unroll 8
        for (int ci = 0; ci < 32; ci++) {
            const float* api = ap + ci * IC_PLANE;
            float a0 = api[0];
            float a1 = api[4 * IC_RS];
            float a2 = api[8 * IC_RS];
            float a3 = api[12 * IC_RS];
            const float* wpi = wp0 + ci * 256;
            ulonglong2 wi = *(const ulonglong2*)(wpi);
            ulonglong2 wf = *(const ulonglong2*)(wpi + 64);
            ulonglong2 wg = *(const ulonglong2*)(wpi + 128);
            ulonglong2 wo = *(const ulonglong2*)(wpi + 192);
            unsigned long long s0 = splat2(a0), s1 = splat2(a1),
                               s2 = splat2(a2), s3 = splat2(a3);
            FMA2(acc[0][0][0], s0, wi.x); FMA2(acc[0][0][1], s0, wi.y);
            FMA2(acc[0][1][0], s0, wf.x); FMA2(acc[0][1][1], s0, wf.y);
            FMA2(acc[0][2][0], s0, wg.x); FMA2(acc[0][2][1], s0, wg.y);
            FMA2(acc[0][3][0], s0, wo.x); FMA2(acc[0][3][1], s0, wo.y);
            FMA2(acc[1][0][0], s1, wi.x); FMA2(acc[1][0][1], s1, wi.y);
            FMA2(acc[1][1][0], s1, wf.x); FMA2(acc[1][1][1], s1, wf.y);
            FMA2(acc[1][2][0], s1, wg.x); FMA2(acc[1][2][1], s1, wg.y);
            FMA2(acc[1][3][0], s1, wo.x); FMA2(acc[1][3][1], s1, wo.y);
            FMA2(acc[2][0][0], s2, wi.x); FMA2(acc[2][0][1], s2, wi.y);
            FMA2(acc[2][1][0], s2, wf.x); FMA2(acc[2][1][1], s2, wf.y);
            FMA2(acc[2][2][0], s2, wg.x); FMA2(acc[2][2][1], s2, wg.y);
            FMA2(acc[2][3][0], s2, wo.x); FMA2(acc[2][3][1], s2, wo.y);
            FMA2(acc[3][0][0], s3, wi.x); FMA2(acc[3][0][1], s3, wi.y);
            FMA2(acc[3][1][0], s3, wf.x); FMA2(acc[3][1][1], s3, wf.y);
            FMA2(acc[3][2][0], s3, wg.x); FMA2(acc[3][2][1], s3, wg.y);
            FMA2(acc[3][3][0], s3, wo.x); FMA2(acc[3][3][1], s3, wo.y);
        }

        __syncthreads();
        if (tap < 8) {
            const float* src = W + (tap + 1) * 8192;
#pragma unroll
            for (int k = 0; k < 4; k++)
                cp16(swu + (unsigned)(tid + k * 512) * 16, src + (tid + k * 512) * 4);
        }
        cp_commit();
    }

    // epilogue: +bias, write gate-grouped xz
    float4 bv[4];
#pragma unroll
    for (int g = 0; g < 4; g++)
        bv[g] = *(const float4*)(bias + 64 * g + 4 * cg);

#pragma unroll
    for (int k = 0; k < 4; k++) {
        int oh = oh0 + r0 + 2 * k, ow = ow0 + c;
        float4* dst = (float4*)(xz + ((((size_t)m * 16 + cg) * H2 + oh) * W2 + ow) * 16);
#pragma unroll
        for (int g = 0; g < 4; g++) {
            float2 p0 = unpack2(acc[k][g][0]);
            float2 p1 = unpack2(acc[k][g][1]);
            dst[g] = make_float4(p0.x + bv[g].x, p0.y + bv[g].y,
                                 p1.x + bv[g].z, p1.y + bv[g].w);
        }
    }
}

// ===========================================================================
// LSTM step: z = conv(h,U,s1 pad1) + xz(bias folded); gates inline; BN out.
// 512 thr = 16 cg x 32 pp; tile 8x16; 4 pos x 16 couts/thread; grid 128.
// s_h [ci][row*48+col] (10x18), PLANE=480 -> conflict-free a-loads.
// ===========================================================================
#define ST_RS 48
#define ST_PLANE 480
#define ST_SH (64 * ST_PLANE)                 // 30720 floats
#define ST_SMEM ((ST_SH + 64 * 256) * 4)      // 188416 B

__global__ __launch_bounds__(512, 1) void lstm_step_kernel(
    const float* __restrict__ hin, float* __restrict__ hout,
    float* __restrict__ cbuf, const float* __restrict__ xz,
    const float* __restrict__ U,
    const float* __restrict__ gamma, const float* __restrict__ beta,
    const float* __restrict__ mmean, const float* __restrict__ mvar,
    float* __restrict__ out, int t)
{
    const int bb  = blockIdx.y;
    const int oh0 = (blockIdx.x >> 2) * 8;
    const int ow0 = (blockIdx.x & 3) * 16;

    extern __shared__ float smem[];
    float* s_h = smem;
    float* s_w = smem + ST_SH;

    const int tid = threadIdx.x;
    const int cg  = tid >> 5;
    const int pp  = tid & 31;
    const int c   = pp & 15;
    const int r0  = pp >> 4;

    // fill halo'd h tile 10x18x64 (col-fastest -> conflict-free STS)
    for (int idx = tid; idx < 10 * 18 * 64; idx += 512) {
        int ci  = idx / 180;
        int sp  = idx - ci * 180;
        int row = sp / 18, col = sp - row * 18;
        int ih = oh0 - 1 + row, iw = ow0 - 1 + col;
        float v = 0.f;
        if (ih >= 0 && ih < H2 && iw >= 0 && iw < W2)
            v = hin[((bb * H2 + ih) * W2 + iw) * FCH + ci];
        s_h[ci * ST_PLANE + row * ST_RS + col] = v;
    }

    // stage tap-0 weights: 16384 floats = 4096 x 16B, 8 per thread
    unsigned swu = (unsigned)__cvta_generic_to_shared(s_w);
#pragma unroll
    for (int k = 0; k < 8; k++)
        cp16(swu + (unsigned)(tid + k * 512) * 16, U + (tid + k * 512) * 4);
    cp_commit();

    unsigned long long acc[4][4][2];
#pragma unroll
    for (int k = 0; k < 4; k++)
#pragma unroll
        for (int g = 0; g < 4; g++) { acc[k][g][0] = 0ull; acc[k][g][1] = 0ull; }

    for (int tap = 0; tap < 9; tap++) {
        cp_wait0();
        __syncthreads();

        const int kh = tap / 3, kw = tap - kh * 3;
        const float* ap  = s_h + (r0 + kh) * ST_RS + c + kw;
        const float* wp0 = s_w + 4 * cg;

#pragma unroll 8
        for (int ci = 0; ci < 64; ci++) {
            const float* api = ap + ci * ST_PLANE;
            float a0 = api[0];
            float a1 = api[2 * ST_RS];
            float a2 = api[4 * ST_RS];
            float a3 = api[6 * ST_RS];
            const float* wpi = wp0 + ci * 256;
            ulonglong2 wi = *(const ulonglong2*)(wpi);
            ulonglong2 wf = *(const ulonglong2*)(wpi + 64);
            ulonglong2 wg = *(const ulonglong2*)(wpi + 128);
            ulonglong2 wo = *(const ulonglong2*)(wpi + 192);
            unsigned long long s0 = splat2(a0), s1 = splat2(a1),
                               s2 = splat2(a2), s3 = splat2(a3);
            FMA2(acc[0][0][0], s0, wi.x); FMA2(acc[0][0][1], s0, wi.y);
            FMA2(acc[0][1][0], s0, wf.x); FMA2(acc[0][1][1], s0, wf.y);
            FMA2(acc[0][2][0], s0, wg.x); FMA2(acc[0][2][1], s0, wg.y);
            FMA2(acc[0][3][0], s0, wo.x); FMA2(acc[0][3][1], s0, wo.y);
            FMA2(acc[1][0][0], s1, wi.x); FMA2(acc[1][0][1], s1, wi.y);
            FMA2(acc[1][1][0], s1, wf.x); FMA2(acc[1][1][1], s1, wf.y);
            FMA2(acc[1][2][0], s1, wg.x); FMA2(acc[1][2][1], s1, wg.y);
            FMA2(acc[1][3][0], s1, wo.x); FMA2(acc[1][3][1], s1, wo.y);
            FMA2(acc[2][0][0], s2, wi.x); FMA2(acc[2][0][1], s2, wi.y);
            FMA2(acc[2][1][0], s2, wf.x); FMA2(acc[2][1][1], s2, wf.y);
            FMA2(acc[2][2][0], s2, wg.x); FMA2(acc[2][2][1], s2, wg.y);
            FMA2(acc[2][3][0], s2, wo.x); FMA2(acc[2][3][1], s2, wo.y);
            FMA2(acc[3][0][0], s3, wi.x); FMA2(acc[3][0][1], s3, wi.y);
            FMA2(acc[3][1][0], s3, wf.x); FMA2(acc[3][1][1], s3, wf.y);
            FMA2(acc[3][2][0], s3, wg.x); FMA2(acc[3][2][1], s3, wg.y);
            FMA2(acc[3][3][0], s3, wo.x); FMA2(acc[3][3][1], s3, wo.y);
        }

        __syncthreads();
        if (tap < 8) {
            const float* src = U + (tap + 1) * 16384;
#pragma unroll
            for (int k = 0; k < 8; k++)
                cp16(swu + (unsigned)(tid + k * 512) * 16, src + (tid + k * 512) * 4);
        }
        cp_commit();
    }

    // ---- epilogue: gates inline, c/h update, BN, stores --------------------
    const int fc0  = 4 * cg;
    const int mimg = bb * TSTEPS + t;
    float4 gm = *(const float4*)(gamma + fc0);
    float4 bt = *(const float4*)(beta + fc0);
    float4 mu = *(const float4*)(mmean + fc0);
    float4 vr = *(const float4*)(mvar + fc0);
    float4 sc = make_float4(gm.x * rsqrtf(vr.x + 1e-3f),
                            gm.y * rsqrtf(vr.y + 1e-3f),
                            gm.z * rsqrtf(vr.z + 1e-3f),
                            gm.w * rsqrtf(vr.w + 1e-3f));

#pragma unroll
    for (int k = 0; k < 4; k++) {
        int oh = oh0 + r0 + 2 * k, ow = ow0 + c;
        const float4* xp = (const float4*)(xz +
            ((((size_t)mimg * 16 + cg) * H2 + oh) * W2 + ow) * 16);
        float4 xi = xp[0], xf = xp[1], xg = xp[2], xo = xp[3];

        float2 i01 = unpack2(acc[k][0][0]), i23 = unpack2(acc[k][0][1]);
        float2 f01 = unpack2(acc[k][1][0]), f23 = unpack2(acc[k][1][1]);
        float2 g01 = unpack2(acc[k][2][0]), g23 = unpack2(acc[k][2][1]);
        float2 o01 = unpack2(acc[k][3][0]), o23 = unpack2(acc[k][3][1]);

        float zi[4] = {i01.x + xi.x, i01.y + xi.y, i23.x + xi.z, i23.y + xi.w};
        float zf[4] = {f01.x + xf.x, f01.y + xf.y, f23.x + xf.z, f23.y + xf.w};
        float zg[4] = {g01.x + xg.x, g01.y + xg.y, g23.x + xg.z, g23.y + xg.w};
        float zo[4] = {o01.x + xo.x, o01.y + xo.y, o23.x + xo.z, o23.y + xo.w};

        size_t sidx = ((size_t)(bb * H2 + oh) * W2 + ow) * FCH + fc0;
        float4 cold = *(const float4*)(cbuf + sidx);
        float co[4] = {cold.x, cold.y, cold.z, cold.w};

        float cn[4], hn[4];
#pragma unroll
        for (int j = 0; j < 4; j++) {
            float gi = hsig(zi[j]);
            float gf = hsig(zf[j]);
            float go = hsig(zo[j]);
            cn[j] = gf * co[j] + gi * tanhf(zg[j]);
            hn[j] = go * tanhf(cn[j]);
        }

        *(float4*)(cbuf + sidx) = make_float4(cn[0], cn[1], cn[2], cn[3]);
        *(float4*)(hout + sidx) = make_float4(hn[0], hn[1], hn[2], hn[3]);

        float4 ov = make_float4((hn[0] - mu.x) * sc.x + bt.x,
                                (hn[1] - mu.y) * sc.y + bt.y,
                                (hn[2] - mu.z) * sc.z + bt.z,
                                (hn[3] - mu.w) * sc.w + bt.w);
        *(float4*)(out + ((((size_t)bb * TSTEPS + t) * H2 + oh) * W2 + ow) * FCH + fc0) = ov;
    }
}

// ---------------------------------------------------------------------------
extern "C" void kernel_launch(void* const* d_in, const int* in_sizes, int n_in,
                              void* d_out, int out_size)
{
    const float* x     = (const float*)d_in[0];
    const float* W     = (const float*)d_in[1];
    const float* U     = (const float*)d_in[2];
    const float* b     = (const float*)d_in[3];
    const float* gamma = (const float*)d_in[4];
    const float* beta  = (const float*)d_in[5];
    const float* mm    = (const float*)d_in[6];
    const float* mv    = (const float*)d_in[7];
    float* out = (float*)d_out;

    float *xz, *hbuf, *cbuf;
    cudaGetSymbolAddress((void**)&xz,   g_xz);
    cudaGetSymbolAddress((void**)&hbuf, g_h);
    cudaGetSymbolAddress((void**)&cbuf, g_c);
    const size_t hsz = (size_t)BATCH * H2 * W2 * FCH;
    float* h0 = hbuf;
    float* h1 = hbuf + hsz;

    cudaFuncSetAttribute(input_conv_kernel,
                         cudaFuncAttributeMaxDynamicSharedMemorySize, IC_SMEM);
    cudaFuncSetAttribute(lstm_step_kernel,
                         cudaFuncAttributeMaxDynamicSharedMemorySize, ST_SMEM);

    cudaMemsetAsync(h0, 0, hsz * sizeof(float));
    cudaMemsetAsync(cbuf, 0, hsz * sizeof(float));

    input_conv_kernel<<<dim3(32, NIMG), 512, IC_SMEM>>>(x, W, b, xz);

    for (int t = 0; t < TSTEPS; t++) {
        const float* hin  = (t & 1) ? h1 : h0;
        float*       hout = (t & 1) ? h0 : h1;
        lstm_step_kernel<<<dim3(32, BATCH), 512, ST_SMEM>>>(
            hin, hout, cbuf, xz, U, gamma, beta, mm, mv, out, t);
    }
}

// round 5
// speedup vs baseline: 5.4052x; 1.8765x over previous
#include <cuda_runtime.h>
#include <cuda_bf16.h>

// ---------------------------------------------------------------------------
// ConvLSTM via mma.sync bf16 hi/lo split (3-pass), fp32 accum. Round 5.
// tcgen05 unavailable (PTX target compute_103 lacks 'a' features), so use
// baseline warp-level tensor core path: ldmatrix + mma.sync.m16n8k16.
// ---------------------------------------------------------------------------

#define H2 64
#define W2 64
#define FCH 64
#define BATCH 4
#define TSTEPS 16
#define NIMG 64

// xz blob in fragment layout: [img][tile32][warp16][reg64][lane32] floats
__device__ float g_xz[(size_t)NIMG * 32 * 16 * 64 * 32];             // 268 MB
__device__ __nv_bfloat16 g_xhi[(size_t)NIMG * 128 * 128 * 32];
__device__ __nv_bfloat16 g_xlo[(size_t)NIMG * 128 * 128 * 32];
__device__ __nv_bfloat16 g_uhi[9 * 256 * 64];    // [tap][n_perm][ci]
__device__ __nv_bfloat16 g_ulo[9 * 256 * 64];
__device__ __nv_bfloat16 g_whi[9 * 256 * 32];    // [tap][n_perm][ci]
__device__ __nv_bfloat16 g_wlo[9 * 256 * 32];
__device__ float g_bperm[256];
__device__ __nv_bfloat16 g_hh[2][(size_t)BATCH * H2 * W2 * FCH];
__device__ __nv_bfloat16 g_hl[2][(size_t)BATCH * H2 * W2 * FCH];
__device__ float g_c[(size_t)BATCH * H2 * W2 * FCH];

// ---------------- helpers ---------------------------------------------------
__device__ __forceinline__ unsigned smem_u32(const void* p) {
    return (unsigned)__cvta_generic_to_shared(p);
}
__device__ __forceinline__ void cp16p(unsigned dst, const void* src, bool p) {
    asm volatile("cp.async.cg.shared.global [%0], [%1], 16, %2;"
                 :: "r"(dst), "l"(src), "r"(p ? 16u : 0u));
}
#define CP_COMMIT() asm volatile("cp.async.commit_group;")
#define CP_WAIT0()  asm volatile("cp.async.wait_group 0;" ::: "memory")

__device__ __forceinline__ unsigned swz(unsigned off) {
    return off ^ ((off >> 3) & 0x70);
}
__device__ __forceinline__ void ldm4(unsigned r[4], unsigned addr) {
    asm volatile("ldmatrix.sync.aligned.m8n8.x4.shared.b16 {%0,%1,%2,%3}, [%4];"
                 : "=r"(r[0]), "=r"(r[1]), "=r"(r[2]), "=r"(r[3]) : "r"(addr));
}
__device__ __forceinline__ void mma16816(float c[4], const unsigned a[4],
                                         unsigned b0, unsigned b1) {
    asm volatile(
        "mma.sync.aligned.m16n8k16.row.col.f32.bf16.bf16.f32 "
        "{%0,%1,%2,%3}, {%4,%5,%6,%7}, {%8,%9}, {%0,%1,%2,%3};"
        : "+f"(c[0]), "+f"(c[1]), "+f"(c[2]), "+f"(c[3])
        : "r"(a[0]), "r"(a[1]), "r"(a[2]), "r"(a[3]), "r"(b0), "r"(b1));
}
__device__ __forceinline__ float hsig(float z) {
    return fminf(fmaxf(0.2f * z + 0.5f, 0.f), 1.f);
}

// smem stages: A_hi 16K | A_lo 16K | B_hi 32K | B_lo 32K = 96K per stage, x2
#define AOFF_LO 16384
#define BOFF_HI 32768
#define BOFF_LO 65536
#define STAGE_SZ 98304
#define SMEM_TOTAL (2 * STAGE_SZ)   // 196608 B

// permutation: cout = g*64 + fc  ->  n = (fc/16)*64 + g*16 + (fc%16)
__host__ __device__ __forceinline__ int perm_n(int cout) {
    int g = cout >> 6, fc = cout & 63;
    return (fc >> 4) * 64 + g * 16 + (fc & 15);
}

// ---------------- prep kernels ---------------------------------------------
__global__ void split_weights_kernel(const float* __restrict__ U,
                                     const float* __restrict__ W,
                                     const float* __restrict__ b) {
    int i = blockIdx.x * 256 + threadIdx.x;
    if (i < 9 * 64 * 256) {
        int tap = i / 16384, r = i % 16384, ci = r >> 8, cout = r & 255;
        int n = perm_n(cout);
        float v = U[i];
        __nv_bfloat16 h = __float2bfloat16(v);
        g_uhi[tap * 16384 + n * 64 + ci] = h;
        g_ulo[tap * 16384 + n * 64 + ci] = __float2bfloat16(v - __bfloat162float(h));
    }
    if (i < 9 * 32 * 256) {
        int tap = i / 8192, r = i % 8192, ci = r >> 8, cout = r & 255;
        int n = perm_n(cout);
        float v = W[i];
        __nv_bfloat16 h = __float2bfloat16(v);
        g_whi[tap * 8192 + n * 32 + ci] = h;
        g_wlo[tap * 8192 + n * 32 + ci] = __float2bfloat16(v - __bfloat162float(h));
    }
    if (i < 256) g_bperm[perm_n(i)] = b[i];
}

__global__ void split_x_kernel(const float* __restrict__ x) {
    size_t i = (size_t)blockIdx.x * 256 + threadIdx.x;
    float v = x[i];
    __nv_bfloat16 h = __float2bfloat16(v);
    g_xhi[i] = h;
    g_xlo[i] = __float2bfloat16(v - __bfloat162float(h));
}

// ---------------- shared compute core --------------------------------------
// 3 passes: (Ah,Bh), (Ah,Bl), (Al,Bh); KC k16-chunks each.
template <int KC>
__device__ __forceinline__ void compute_tap(unsigned st, int mw, int nw,
                                            int lane, float acc[2][8][4]) {
    const int arow  = (lane & 7) + ((lane >> 3) & 1) * 8;
    const int abyte = ((lane >> 4) & 1) * 16;
    const int brow  = (lane & 7) + ((lane >> 4) & 1) * 8;
    const int bbyte = ((lane >> 3) & 1) * 16;
    const unsigned apos[3] = {0u, 0u, AOFF_LO};
    const unsigned bpos[3] = {BOFF_HI, BOFF_LO, BOFF_HI};
#pragma unroll
    for (int ps = 0; ps < 3; ps++) {
        unsigned Ab = st + apos[ps], Bb = st + bpos[ps];
#pragma unroll
        for (int k = 0; k < KC; k++) {
            unsigned a0[4], a1[4];
            ldm4(a0, Ab + swz((unsigned)(mw * 32 + arow) * 128 + k * 32 + abyte));
            ldm4(a1, Ab + swz((unsigned)(mw * 32 + 16 + arow) * 128 + k * 32 + abyte));
            unsigned b[4][4];
#pragma unroll
            for (int t = 0; t < 4; t++)
                ldm4(b[t], Bb + swz((unsigned)(nw * 64 + t * 16 + brow) * 128 + k * 32 + bbyte));
#pragma unroll
            for (int t = 0; t < 4; t++) {
                mma16816(acc[0][2 * t],     a0, b[t][0], b[t][1]);
                mma16816(acc[0][2 * t + 1], a0, b[t][2], b[t][3]);
                mma16816(acc[1][2 * t],     a1, b[t][0], b[t][1]);
                mma16816(acc[1][2 * t + 1], a1, b[t][2], b[t][3]);
            }
        }
    }
}

// ---------------- input conv ------------------------------------------------
__device__ __forceinline__ void fill_ic(unsigned st, int tap, int mimg,
                                        int oh0, int ow0, int tid) {
    const int kh = tap / 3, kw = tap - kh * 3;
    // A: 128 rows x 4 x16B, hi+lo = 1024 tasks
    for (int i = tid; i < 1024; i += 512) {
        int hl = i >> 9, rem = i & 511, row = rem >> 2, j = rem & 3;
        int oh = oh0 + (row >> 4), ow = ow0 + (row & 15);
        int ih = 2 * oh + kh, iw = 2 * ow + kw;
        bool ok = (ih < 128 && iw < 128);
        const __nv_bfloat16* src = (hl ? g_xlo : g_xhi) +
            (((size_t)mimg * 128 + (ok ? ih : 0)) * 128 + (ok ? iw : 0)) * 32 + j * 8;
        cp16p(st + (hl ? AOFF_LO : 0u) + swz((unsigned)row * 128 + j * 16), src, ok);
    }
    // B: 256 rows x 4 x16B, hi+lo = 2048 tasks
    for (int i = tid; i < 2048; i += 512) {
        int hl = i >> 10, rem = i & 1023, row = rem >> 2, j = rem & 3;
        const __nv_bfloat16* src = (hl ? g_wlo : g_whi) + tap * 8192 + row * 32 + j * 8;
        cp16p(st + (hl ? BOFF_LO : BOFF_HI) + swz((unsigned)row * 128 + j * 16), src, true);
    }
    CP_COMMIT();
}

__global__ __launch_bounds__(512, 1) void ic_mma_kernel(float* __restrict__ xz)
{
    extern __shared__ __align__(1024) char smem[];
    unsigned sb = smem_u32(smem);
    const int tid = threadIdx.x, lane = tid & 31, wid = tid >> 5;
    const int mw = wid >> 2, nw = wid & 3;
    const int mimg = blockIdx.y;
    const int oh0 = (blockIdx.x >> 2) * 8, ow0 = (blockIdx.x & 3) * 16;

    float acc[2][8][4];
#pragma unroll
    for (int a = 0; a < 2; a++)
#pragma unroll
        for (int b = 0; b < 8; b++)
#pragma unroll
            for (int c = 0; c < 4; c++) acc[a][b][c] = 0.f;

    fill_ic(sb, 0, mimg, oh0, ow0, tid);
    for (int tap = 0; tap < 9; tap++) {
        CP_WAIT0();
        __syncthreads();
        if (tap < 8)
            fill_ic(sb + ((tap + 1) & 1) * STAGE_SZ, tap + 1, mimg, oh0, ow0, tid);
        compute_tap<2>(sb + (tap & 1) * STAGE_SZ, mw, nw, lane, acc);
    }

    // epilogue: +bias, store fragment blob
    float2 bv[8];
#pragma unroll
    for (int nn = 0; nn < 8; nn++)
        bv[nn] = *(const float2*)(g_bperm + nw * 64 + nn * 8 + 2 * (lane & 3));
    float* blob = xz + (((size_t)mimg * 32 + blockIdx.x) * 16 + wid) * 2048 + lane;
#pragma unroll
    for (int mi = 0; mi < 2; mi++)
#pragma unroll
        for (int nn = 0; nn < 8; nn++)
#pragma unroll
            for (int rg = 0; rg < 4; rg++)
                blob[((mi * 8 + nn) * 4 + rg) * 32] =
                    acc[mi][nn][rg] + ((rg & 1) ? bv[nn].y : bv[nn].x);
}

// ---------------- LSTM step -------------------------------------------------
__device__ __forceinline__ void fill_step(unsigned st, int tap,
    const __nv_bfloat16* hh, const __nv_bfloat16* hl,
    int bb, int oh0, int ow0, int tid)
{
    const int kh = tap / 3, kw = tap - kh * 3;
    // A: 128 rows x 8 x16B, hi+lo = 2048 tasks
    for (int i = tid; i < 2048; i += 512) {
        int hlsel = i >> 10, rem = i & 1023, row = rem >> 3, j = rem & 7;
        int oh = oh0 + (row >> 4), ow = ow0 + (row & 15);
        int ih = oh - 1 + kh, iw = ow - 1 + kw;
        bool ok = (ih >= 0 && ih < H2 && iw >= 0 && iw < W2);
        const __nv_bfloat16* src = (hlsel ? hl : hh) +
            (((size_t)bb * H2 + (ok ? ih : 0)) * W2 + (ok ? iw : 0)) * FCH + j * 8;
        cp16p(st + (hlsel ? AOFF_LO : 0u) + swz((unsigned)row * 128 + j * 16), src, ok);
    }
    // B: 256 rows x 8 x16B, hi+lo = 4096 tasks
    for (int i = tid; i < 4096; i += 512) {
        int hlsel = i >> 11, rem = i & 2047, row = rem >> 3, j = rem & 7;
        const __nv_bfloat16* src = (hlsel ? g_ulo : g_uhi) + tap * 16384 + row * 64 + j * 8;
        cp16p(st + (hlsel ? BOFF_LO : BOFF_HI) + swz((unsigned)row * 128 + j * 16), src, true);
    }
    CP_COMMIT();
}

__global__ __launch_bounds__(512, 1) void lstm_step_mma(
    const __nv_bfloat16* __restrict__ hh, const __nv_bfloat16* __restrict__ hl,
    __nv_bfloat16* __restrict__ hho, __nv_bfloat16* __restrict__ hlo,
    float* __restrict__ cbuf, const float* __restrict__ xz,
    const float* __restrict__ gamma, const float* __restrict__ beta,
    const float* __restrict__ mmean, const float* __restrict__ mvar,
    float* __restrict__ out, int t)
{
    extern __shared__ __align__(1024) char smem[];
    unsigned sb = smem_u32(smem);
    const int tid = threadIdx.x, lane = tid & 31, wid = tid >> 5;
    const int mw = wid >> 2, nw = wid & 3;
    const int bb = blockIdx.y;
    const int oh0 = (blockIdx.x >> 2) * 8, ow0 = (blockIdx.x & 3) * 16;

    float acc[2][8][4];
#pragma unroll
    for (int a = 0; a < 2; a++)
#pragma unroll
        for (int b = 0; b < 8; b++)
#pragma unroll
            for (int c = 0; c < 4; c++) acc[a][b][c] = 0.f;

    fill_step(sb, 0, hh, hl, bb, oh0, ow0, tid);
    for (int tap = 0; tap < 9; tap++) {
        CP_WAIT0();
        __syncthreads();
        if (tap < 8)
            fill_step(sb + ((tap + 1) & 1) * STAGE_SZ, tap + 1, hh, hl, bb, oh0, ow0, tid);
        compute_tap<4>(sb + (tap & 1) * STAGE_SZ, mw, nw, lane, acc);
    }

    // add xz (bias folded)
    const float* blob = xz +
        (((size_t)(bb * TSTEPS + t) * 32 + blockIdx.x) * 16 + wid) * 2048 + lane;
#pragma unroll
    for (int mi = 0; mi < 2; mi++)
#pragma unroll
        for (int nn = 0; nn < 8; nn++)
#pragma unroll
            for (int rg = 0; rg < 4; rg++)
                acc[mi][nn][rg] += blob[((mi * 8 + nn) * 4 + rg) * 32];

    // gates: lane owns fc = nw*16 + p*8 + 2*(lane&3) + q, all 4 gates in-reg:
    // z_g[q] = acc[mi][g*2+p][rb*2+q]
#pragma unroll
    for (int p = 0; p < 2; p++) {
        const int fcb = nw * 16 + p * 8 + 2 * (lane & 3);
        float2 gm = *(const float2*)(gamma + fcb);
        float2 bt = *(const float2*)(beta + fcb);
        float2 mu = *(const float2*)(mmean + fcb);
        float2 vr = *(const float2*)(mvar + fcb);
        float sc0 = gm.x * rsqrtf(vr.x + 1e-3f);
        float sc1 = gm.y * rsqrtf(vr.y + 1e-3f);
#pragma unroll
        for (int mi = 0; mi < 2; mi++) {
#pragma unroll
            for (int rb = 0; rb < 2; rb++) {
                int oh = oh0 + mw * 2 + mi;
                int ow = ow0 + rb * 8 + (lane >> 2);
                size_t sidx = (((size_t)bb * H2 + oh) * W2 + ow) * FCH + fcb;
                float2 cc = *(const float2*)(cbuf + sidx);

                float cn[2], hn[2], ov[2];
#pragma unroll
                for (int q = 0; q < 2; q++) {
                    float zi = acc[mi][0 + p][rb * 2 + q];
                    float zf = acc[mi][2 + p][rb * 2 + q];
                    float zg = acc[mi][4 + p][rb * 2 + q];
                    float zo = acc[mi][6 + p][rb * 2 + q];
                    float co = q ? cc.y : cc.x;
                    float c2 = hsig(zf) * co + hsig(zi) * tanhf(zg);
                    hn[q] = hsig(zo) * tanhf(c2);
                    cn[q] = c2;
                    float s = q ? sc1 : sc0;
                    ov[q] = (hn[q] - (q ? mu.y : mu.x)) * s + (q ? bt.y : bt.x);
                }
                *(float2*)(cbuf + sidx) = make_float2(cn[0], cn[1]);

                __nv_bfloat16 h0 = __float2bfloat16(hn[0]);
                __nv_bfloat16 h1 = __float2bfloat16(hn[1]);
                __nv_bfloat16 l0 = __float2bfloat16(hn[0] - __bfloat162float(h0));
                __nv_bfloat16 l1 = __float2bfloat16(hn[1] - __bfloat162float(h1));
                unsigned hp = ((unsigned)*(unsigned short*)&h1 << 16) |
                              *(unsigned short*)&h0;
                unsigned lp = ((unsigned)*(unsigned short*)&l1 << 16) |
                              *(unsigned short*)&l0;
                *(unsigned*)(hho + sidx) = hp;
                *(unsigned*)(hlo + sidx) = lp;

                *(float2*)(out + ((((size_t)bb * TSTEPS + t) * H2 + oh) * W2 + ow) * FCH + fcb)
                    = make_float2(ov[0], ov[1]);
            }
        }
    }
}

// ---------------------------------------------------------------------------
extern "C" void kernel_launch(void* const* d_in, const int* in_sizes, int n_in,
                              void* d_out, int out_size)
{
    const float* x     = (const float*)d_in[0];
    const float* W     = (const float*)d_in[1];
    const float* U     = (const float*)d_in[2];
    const float* b     = (const float*)d_in[3];
    const float* gamma = (const float*)d_in[4];
    const float* beta  = (const float*)d_in[5];
    const float* mm    = (const float*)d_in[6];
    const float* mv    = (const float*)d_in[7];
    float* out = (float*)d_out;

    float *xz, *cbuf;
    __nv_bfloat16 *hh, *hl;
    cudaGetSymbolAddress((void**)&xz, g_xz);
    cudaGetSymbolAddress((void**)&cbuf, g_c);
    cudaGetSymbolAddress((void**)&hh, g_hh);
    cudaGetSymbolAddress((void**)&hl, g_hl);
    const size_t hsz = (size_t)BATCH * H2 * W2 * FCH;

    cudaFuncSetAttribute(ic_mma_kernel,
                         cudaFuncAttributeMaxDynamicSharedMemorySize, SMEM_TOTAL);
    cudaFuncSetAttribute(lstm_step_mma,
                         cudaFuncAttributeMaxDynamicSharedMemorySize, SMEM_TOTAL);

    cudaMemsetAsync(hh, 0, hsz * sizeof(__nv_bfloat16));
    cudaMemsetAsync(hl, 0, hsz * sizeof(__nv_bfloat16));
    cudaMemsetAsync(cbuf, 0, hsz * sizeof(float));

    split_weights_kernel<<<576, 256>>>(U, W, b);
    split_x_kernel<<<131072, 256>>>(x);
    ic_mma_kernel<<<dim3(32, NIMG), 512, SMEM_TOTAL>>>(xz);

    for (int t = 0; t < TSTEPS; t++) {
        int rd = t & 1, wr = (t + 1) & 1;
        lstm_step_mma<<<dim3(32, BATCH), 512, SMEM_TOTAL>>>(
            hh + rd * hsz, hl + rd * hsz, hh + wr * hsz, hl + wr * hsz,
            cbuf, xz, gamma, beta, mm, mv, out, t);
    }
}

// round 7
// speedup vs baseline: 5.4297x; 1.0045x over previous
#include <cuda_runtime.h>
#include <cuda_bf16.h>

// ---------------------------------------------------------------------------
// ConvLSTM, mma.sync bf16 hi/lo 3-pass. Round 6 resubmit (infra flake):
// 2 CTA/SM, A staged once (direct ldmatrix with per-tap lane addresses),
// N=128 per CTA, gate-perm v2.
// ---------------------------------------------------------------------------

#define H2 64
#define W2 64
#define FCH 64
#define BATCH 4
#define TSTEPS 16
#define NIMG 64

// xz blob: [img][mt32][nh2][warp8][frag64][lane32] floats
__device__ float g_xz[(size_t)NIMG * 32 * 2 * 8 * 64 * 32];          // 268 MB
__device__ __nv_bfloat16 g_xhi[(size_t)NIMG * 128 * 128 * 32];
__device__ __nv_bfloat16 g_xlo[(size_t)NIMG * 128 * 128 * 32];
__device__ __nv_bfloat16 g_uhi[9 * 256 * 64];    // [tap][n_perm][ci]
__device__ __nv_bfloat16 g_ulo[9 * 256 * 64];
__device__ __nv_bfloat16 g_whi[9 * 256 * 32];    // [tap][n_perm][ci]
__device__ __nv_bfloat16 g_wlo[9 * 256 * 32];
__device__ float g_bperm[256];
__device__ __nv_bfloat16 g_hh[2][(size_t)BATCH * H2 * W2 * FCH];
__device__ __nv_bfloat16 g_hl[2][(size_t)BATCH * H2 * W2 * FCH];
__device__ float g_c[(size_t)BATCH * H2 * W2 * FCH];

// ---------------- helpers ---------------------------------------------------
__device__ __forceinline__ unsigned smem_u32(const void* p) {
    return (unsigned)__cvta_generic_to_shared(p);
}
__device__ __forceinline__ void cp16p(unsigned dst, const void* src, bool p) {
    asm volatile("cp.async.cg.shared.global [%0], [%1], 16, %2;"
                 :: "r"(dst), "l"(src), "r"(p ? 16u : 0u));
}
#define CP_COMMIT() asm volatile("cp.async.commit_group;")
#define CP_WAIT0()  asm volatile("cp.async.wait_group 0;" ::: "memory")

__device__ __forceinline__ unsigned swz(unsigned off) {
    return off ^ ((off >> 3) & 0x70);
}
__device__ __forceinline__ void ldm4(unsigned r[4], unsigned addr) {
    asm volatile("ldmatrix.sync.aligned.m8n8.x4.shared.b16 {%0,%1,%2,%3}, [%4];"
                 : "=r"(r[0]), "=r"(r[1]), "=r"(r[2]), "=r"(r[3]) : "r"(addr));
}
__device__ __forceinline__ void mma16816(float c[4], const unsigned a[4],
                                         unsigned b0, unsigned b1) {
    asm volatile(
        "mma.sync.aligned.m16n8k16.row.col.f32.bf16.bf16.f32 "
        "{%0,%1,%2,%3}, {%4,%5,%6,%7}, {%8,%9}, {%0,%1,%2,%3};"
        : "+f"(c[0]), "+f"(c[1]), "+f"(c[2]), "+f"(c[3])
        : "r"(a[0]), "r"(a[1]), "r"(a[2]), "r"(a[3]), "r"(b0), "r"(b1));
}
__device__ __forceinline__ float hsig(float z) {
    return fminf(fmaxf(0.2f * z + 0.5f, 0.f), 1.f);
}

// perm v2: cout = g*64+fc -> n = (fc>>3)*32 + g*8 + (fc&7)
__host__ __device__ __forceinline__ int perm_n(int cout) {
    int g = cout >> 6, fc = cout & 63;
    return (fc >> 3) * 32 + g * 8 + (fc & 7);
}

// step smem: A_hi[0:23040) A_lo[23040:46080) B stages at 46080 + s*32768
#define SA_LO 23040
#define SB_BASE 46080
#define SB_STAGE 32768
#define SB_LO 16384
#define ST_SMEM 111616
// ic smem: per stage 40960: A_hi 0, A_lo 10240, B_hi 20480, B_lo 30720
#define IC_STAGE 40960
#define IC_SMEM 81920

// ---------------- prep kernels ---------------------------------------------
__global__ void split_weights_kernel(const float* __restrict__ U,
                                     const float* __restrict__ W,
                                     const float* __restrict__ b) {
    int i = blockIdx.x * 256 + threadIdx.x;
    if (i < 9 * 64 * 256) {
        int tap = i / 16384, r = i % 16384, ci = r >> 8, cout = r & 255;
        int n = perm_n(cout);
        float v = U[i];
        __nv_bfloat16 h = __float2bfloat16(v);
        g_uhi[tap * 16384 + n * 64 + ci] = h;
        g_ulo[tap * 16384 + n * 64 + ci] = __float2bfloat16(v - __bfloat162float(h));
    }
    if (i < 9 * 32 * 256) {
        int tap = i / 8192, r = i % 8192, ci = r >> 8, cout = r & 255;
        int n = perm_n(cout);
        float v = W[i];
        __nv_bfloat16 h = __float2bfloat16(v);
        g_whi[tap * 8192 + n * 32 + ci] = h;
        g_wlo[tap * 8192 + n * 32 + ci] = __float2bfloat16(v - __bfloat162float(h));
    }
    if (i < 256) g_bperm[perm_n(i)] = b[i];
}

__global__ void split_x_kernel(const float* __restrict__ x) {
    size_t i = (size_t)blockIdx.x * 256 + threadIdx.x;
    float v = x[i];
    __nv_bfloat16 h = __float2bfloat16(v);
    g_xhi[i] = h;
    g_xlo[i] = __float2bfloat16(v - __bfloat162float(h));
}

// ---------------- input conv ------------------------------------------------
__device__ __forceinline__ void fill_ic(unsigned st, int tap, int img, int nh,
                                        int oh0, int ow0, int tid) {
    const int kh = tap / 3, kw = tap - kh * 3;
    // A im2col (80B-padded rows): 2 x 128 rows x 4 chunks
    for (int i = tid; i < 1024; i += 256) {
        int hl = i >> 9, rem = i & 511, row = rem >> 2, j = rem & 3;
        int srow = row >> 4, scol = row & 15;
        int ih = 2 * (oh0 + srow) + kh, iw = 2 * (ow0 + scol) + kw;
        bool ok = (ih < 128 && iw < 128);
        const __nv_bfloat16* s = (hl ? g_xlo : g_xhi) +
            (((size_t)img * 128 + (ok ? ih : 0)) * 128 + (ok ? iw : 0)) * 32 + j * 8;
        cp16p(st + hl * 10240 + row * 80 + j * 16, s, ok);
    }
    // B (80B-padded rows): 2 x 128 rows x 4 chunks
    for (int i = tid; i < 1024; i += 256) {
        int hl = i >> 9, rem = i & 511, n = rem >> 2, j = rem & 3;
        const __nv_bfloat16* s = (hl ? g_wlo : g_whi) +
            tap * 8192 + (nh * 128 + n) * 32 + j * 8;
        cp16p(st + 20480 + hl * 10240 + n * 80 + j * 16, s, true);
    }
    CP_COMMIT();
}

__global__ __launch_bounds__(256, 2) void ic_mma_kernel(float* __restrict__ xz)
{
    extern __shared__ __align__(1024) char smem[];
    unsigned sb = smem_u32(smem);
    const int tid = threadIdx.x, lane = tid & 31, wid = tid >> 5;
    const int mw = wid >> 2, nw = wid & 3;
    const int mt = blockIdx.x;
    const int img = blockIdx.y >> 1, nh = blockIdx.y & 1;
    const int oh0 = (mt >> 2) * 8, ow0 = (mt & 3) * 16;

    const int arow = (lane & 7) + ((lane >> 3) & 1) * 8;
    const int abyte = ((lane >> 4) & 1) * 16;
    const int brow = (lane & 7) + ((lane >> 4) & 1) * 8;
    const int bbyte = ((lane >> 3) & 1) * 16;

    int abase[4], bbase[2];
#pragma unroll
    for (int mf = 0; mf < 4; mf++)
        abase[mf] = (mw * 64 + mf * 16 + arow) * 80 + abyte;
#pragma unroll
    for (int p = 0; p < 2; p++)
        bbase[p] = 20480 + (nw * 32 + p * 16 + brow) * 80 + bbyte;

    float acc[4][4][4];
#pragma unroll
    for (int a = 0; a < 4; a++)
#pragma unroll
        for (int b = 0; b < 4; b++)
#pragma unroll
            for (int c = 0; c < 4; c++) acc[a][b][c] = 0.f;

    fill_ic(sb, 0, img, nh, oh0, ow0, tid);
    for (int tap = 0; tap < 9; tap++) {
        CP_WAIT0();
        __syncthreads();
        if (tap < 8)
            fill_ic(sb + ((tap + 1) & 1) * IC_STAGE, tap + 1, img, nh, oh0, ow0, tid);
        unsigned st = sb + (tap & 1) * IC_STAGE;
#pragma unroll
        for (int ps = 0; ps < 3; ps++) {
            unsigned Ao = (ps == 2) ? 10240u : 0u;
            unsigned Bo = (ps == 1) ? 10240u : 0u;
#pragma unroll
            for (int k = 0; k < 2; k++) {
                unsigned a[4][4], b[2][4];
#pragma unroll
                for (int mf = 0; mf < 4; mf++)
                    ldm4(a[mf], st + Ao + (unsigned)(abase[mf] + k * 32));
#pragma unroll
                for (int p = 0; p < 2; p++)
                    ldm4(b[p], st + Bo + (unsigned)(bbase[p] + k * 32));
#pragma unroll
                for (int mf = 0; mf < 4; mf++)
#pragma unroll
                    for (int p = 0; p < 2; p++) {
                        mma16816(acc[mf][2 * p],     a[mf], b[p][0], b[p][1]);
                        mma16816(acc[mf][2 * p + 1], a[mf], b[p][2], b[p][3]);
                    }
            }
        }
    }

    // epilogue: +bias(perm), write fragment blob
    float2 bv[4];
#pragma unroll
    for (int nf = 0; nf < 4; nf++)
        bv[nf] = *(const float2*)(g_bperm + nh * 128 + nw * 32 + nf * 8 + 2 * (lane & 3));
    float* blob = xz + ((((size_t)img * 32 + mt) * 2 + nh) * 8 + wid) * 2048 + lane;
#pragma unroll
    for (int mf = 0; mf < 4; mf++)
#pragma unroll
        for (int nf = 0; nf < 4; nf++)
#pragma unroll
            for (int r = 0; r < 4; r++)
                blob[((mf * 4 + nf) * 4 + r) * 32] =
                    acc[mf][nf][r] + ((r & 1) ? bv[nf].y : bv[nf].x);
}

// ---------------- LSTM step -------------------------------------------------
__device__ __forceinline__ void fill_b_step(unsigned dst, int tap, int nh, int tid) {
    const __nv_bfloat16* uh = g_uhi + tap * 16384 + nh * 128 * 64;
    const __nv_bfloat16* ul = g_ulo + tap * 16384 + nh * 128 * 64;
    for (int i = tid; i < 2048; i += 256) {
        int hl = i >> 10, rem = i & 1023, n = rem >> 3, j = rem & 7;
        const __nv_bfloat16* s = (hl ? ul : uh) + n * 64 + j * 8;
        cp16p(dst + hl * SB_LO + swz((unsigned)(n * 128 + j * 16)), s, true);
    }
    CP_COMMIT();
}

__global__ __launch_bounds__(256, 2) void lstm_step_mma(
    const __nv_bfloat16* __restrict__ hh, const __nv_bfloat16* __restrict__ hl,
    __nv_bfloat16* __restrict__ hho, __nv_bfloat16* __restrict__ hlo,
    float* __restrict__ cbuf, const float* __restrict__ xz,
    const float* __restrict__ gamma, const float* __restrict__ beta,
    const float* __restrict__ mmean, const float* __restrict__ mvar,
    float* __restrict__ out, int t)
{
    extern __shared__ __align__(1024) char smem[];
    unsigned sb = smem_u32(smem);
    const int tid = threadIdx.x, lane = tid & 31, wid = tid >> 5;
    const int mw = wid >> 2, nw = wid & 3;
    const int mt = blockIdx.x;
    const int bb = blockIdx.y >> 1, nh = blockIdx.y & 1;
    const int oh0 = (mt >> 2) * 8, ow0 = (mt & 3) * 16;

    // A: halo'd h tile 10x18 rows of 128B, hi+lo, SW128; filled once
    for (int i = tid; i < 2880; i += 256) {
        int hlsel = (i >= 1440) ? 1 : 0;
        int rem = i - hlsel * 1440;
        int row = rem >> 3, j = rem & 7;
        int hr = row / 18, hc = row - hr * 18;
        int ih = oh0 - 1 + hr, iw = ow0 - 1 + hc;
        bool ok = (ih >= 0 && ih < H2 && iw >= 0 && iw < W2);
        const __nv_bfloat16* s = (hlsel ? hl : hh) +
            (((size_t)bb * H2 + (ok ? ih : 0)) * W2 + (ok ? iw : 0)) * FCH + j * 8;
        cp16p(sb + hlsel * SA_LO + swz((unsigned)(row * 128 + j * 16)), s, ok);
    }
    fill_b_step(sb + SB_BASE, 0, nh, tid);   // commits A+B0 together

    const int arow = (lane & 7) + ((lane >> 3) & 1) * 8;
    const int abyte = ((lane >> 4) & 1) * 16;
    const int brow = (lane & 7) + ((lane >> 4) & 1) * 8;
    const int bbyte = ((lane >> 3) & 1) * 16;

    int abase[4], bbase[2];
#pragma unroll
    for (int mf = 0; mf < 4; mf++)   // spatial row = mw*4+mf, col = arow
        abase[mf] = ((mw * 4 + mf) * 18 + arow) * 128 + abyte;
#pragma unroll
    for (int p = 0; p < 2; p++)
        bbase[p] = (nw * 32 + p * 16 + brow) * 128 + bbyte;

    float acc[4][4][4];
#pragma unroll
    for (int a = 0; a < 4; a++)
#pragma unroll
        for (int b = 0; b < 4; b++)
#pragma unroll
            for (int c = 0; c < 4; c++) acc[a][b][c] = 0.f;

    for (int tap = 0; tap < 9; tap++) {
        CP_WAIT0();
        __syncthreads();
        if (tap < 8)
            fill_b_step(sb + SB_BASE + ((tap + 1) & 1) * SB_STAGE, tap + 1, nh, tid);
        const int kh = tap / 3, kw = tap - kh * 3;
        const int toff = (kh * 18 + kw) * 128;
        unsigned Bst = sb + SB_BASE + (tap & 1) * SB_STAGE;
#pragma unroll
        for (int ps = 0; ps < 3; ps++) {
            unsigned Ab = sb + ((ps == 2) ? SA_LO : 0u);
            unsigned Bb = Bst + ((ps == 1) ? SB_LO : 0u);
#pragma unroll
            for (int k = 0; k < 4; k++) {
                unsigned a[4][4], b[2][4];
#pragma unroll
                for (int mf = 0; mf < 4; mf++)
                    ldm4(a[mf], Ab + swz((unsigned)(abase[mf] + toff + k * 32)));
#pragma unroll
                for (int p = 0; p < 2; p++)
                    ldm4(b[p], Bb + swz((unsigned)(bbase[p] + k * 32)));
#pragma unroll
                for (int mf = 0; mf < 4; mf++)
#pragma unroll
                    for (int p = 0; p < 2; p++) {
                        mma16816(acc[mf][2 * p],     a[mf], b[p][0], b[p][1]);
                        mma16816(acc[mf][2 * p + 1], a[mf], b[p][2], b[p][3]);
                    }
            }
        }
    }

    // add xz (bias folded)
    const float* blob = xz +
        ((((size_t)(bb * TSTEPS + t) * 32 + mt) * 2 + nh) * 8 + wid) * 2048 + lane;
#pragma unroll
    for (int mf = 0; mf < 4; mf++)
#pragma unroll
        for (int nf = 0; nf < 4; nf++)
#pragma unroll
            for (int r = 0; r < 4; r++)
                acc[mf][nf][r] += blob[((mf * 4 + nf) * 4 + r) * 32];

    // gates in-register: lane fc pair = fc0, fc0+1; nf = gate
    const int fc0 = (nh * 4 + nw) * 8 + 2 * (lane & 3);
    float2 gm = *(const float2*)(gamma + fc0);
    float2 bt = *(const float2*)(beta + fc0);
    float2 mu = *(const float2*)(mmean + fc0);
    float2 vr = *(const float2*)(mvar + fc0);
    float sc0 = gm.x * rsqrtf(vr.x + 1e-3f);
    float sc1 = gm.y * rsqrtf(vr.y + 1e-3f);

#pragma unroll
    for (int mf = 0; mf < 4; mf++) {
        int oh = oh0 + mw * 4 + mf;
#pragma unroll
        for (int rh = 0; rh < 2; rh++) {
            int ow = ow0 + (lane >> 2) + 8 * rh;
            size_t sidx = (((size_t)bb * H2 + oh) * W2 + ow) * FCH + fc0;
            float2 cc = *(const float2*)(cbuf + sidx);
            float cn[2], hn[2], ov[2];
#pragma unroll
            for (int q = 0; q < 2; q++) {
                float zi = acc[mf][0][2 * rh + q];
                float zf = acc[mf][1][2 * rh + q];
                float zg = acc[mf][2][2 * rh + q];
                float zo = acc[mf][3][2 * rh + q];
                float co = q ? cc.y : cc.x;
                float c2 = hsig(zf) * co + hsig(zi) * tanhf(zg);
                hn[q] = hsig(zo) * tanhf(c2);
                cn[q] = c2;
                float s = q ? sc1 : sc0;
                ov[q] = (hn[q] - (q ? mu.y : mu.x)) * s + (q ? bt.y : bt.x);
            }
            *(float2*)(cbuf + sidx) = make_float2(cn[0], cn[1]);

            __nv_bfloat16 h0 = __float2bfloat16(hn[0]);
            __nv_bfloat16 h1 = __float2bfloat16(hn[1]);
            __nv_bfloat16 l0 = __float2bfloat16(hn[0] - __bfloat162float(h0));
            __nv_bfloat16 l1 = __float2bfloat16(hn[1] - __bfloat162float(h1));
            unsigned hp = ((unsigned)*(unsigned short*)&h1 << 16) | *(unsigned short*)&h0;
            unsigned lp = ((unsigned)*(unsigned short*)&l1 << 16) | *(unsigned short*)&l0;
            *(unsigned*)(hho + sidx) = hp;
            *(unsigned*)(hlo + sidx) = lp;

            *(float2*)(out + ((((size_t)bb * TSTEPS + t) * H2 + oh) * W2 + ow) * FCH + fc0)
                = make_float2(ov[0], ov[1]);
        }
    }
}

// ---------------------------------------------------------------------------
extern "C" void kernel_launch(void* const* d_in, const int* in_sizes, int n_in,
                              void* d_out, int out_size)
{
    const float* x     = (const float*)d_in[0];
    const float* W     = (const float*)d_in[1];
    const float* U     = (const float*)d_in[2];
    const float* b     = (const float*)d_in[3];
    const float* gamma = (const float*)d_in[4];
    const float* beta  = (const float*)d_in[5];
    const float* mm    = (const float*)d_in[6];
    const float* mv    = (const float*)d_in[7];
    float* out = (float*)d_out;

    float *xz, *cbuf;
    __nv_bfloat16 *hh, *hl;
    cudaGetSymbolAddress((void**)&xz, g_xz);
    cudaGetSymbolAddress((void**)&cbuf, g_c);
    cudaGetSymbolAddress((void**)&hh, g_hh);
    cudaGetSymbolAddress((void**)&hl, g_hl);
    const size_t hsz = (size_t)BATCH * H2 * W2 * FCH;

    cudaFuncSetAttribute(ic_mma_kernel,
                         cudaFuncAttributeMaxDynamicSharedMemorySize, IC_SMEM);
    cudaFuncSetAttribute(lstm_step_mma,
                         cudaFuncAttributeMaxDynamicSharedMemorySize, ST_SMEM);

    cudaMemsetAsync(hh, 0, hsz * sizeof(__nv_bfloat16));
    cudaMemsetAsync(hl, 0, hsz * sizeof(__nv_bfloat16));
    cudaMemsetAsync(cbuf, 0, hsz * sizeof(float));

    split_weights_kernel<<<576, 256>>>(U, W, b);
    split_x_kernel<<<131072, 256>>>(x);
    ic_mma_kernel<<<dim3(32, 128), 256, IC_SMEM>>>(xz);

    for (int t = 0; t < TSTEPS; t++) {
        int rd = t & 1, wr = (t + 1) & 1;
        lstm_step_mma<<<dim3(32, 8), 256, ST_SMEM>>>(
            hh + rd * hsz, hl + rd * hsz, hh + wr * hsz, hl + wr * hsz,
            cbuf, xz, gamma, beta, mm, mv, out, t);
    }
}

// round 8
// speedup vs baseline: 9.0438x; 1.6656x over previous
#include <cuda_runtime.h>
#include <cuda_bf16.h>

// ---------------------------------------------------------------------------
// ConvLSTM via mma.sync tf32 SINGLE-pass, fp32 accum. Round 8.
// All operands pre-rounded to tf32 (cvt.rna) -> in-kernel loads are plain f32.
// XOR-granule swizzled smem (chunk ^= row&7), scalar ld.shared frag loads.
// ---------------------------------------------------------------------------

#define H2 64
#define W2 64
#define FCH 64
#define BATCH 4
#define TSTEPS 16
#define NIMG 64

// xz blob: [img][mt32][nh2][warp8][frag64][lane32] floats
__device__ float g_xz[(size_t)NIMG * 32 * 2 * 8 * 64 * 32];          // 268 MB
__device__ float g_xt[(size_t)NIMG * 128 * 128 * 32];                // 134 MB
__device__ float g_ut[9 * 256 * 64];     // [tap][n_perm][ci], tf32-rounded
__device__ float g_wt[9 * 256 * 32];     // [tap][n_perm][ci]
__device__ float g_bperm[256];
__device__ float g_ht[2][(size_t)BATCH * H2 * W2 * FCH];             // 2 x 4 MB
__device__ float g_c[(size_t)BATCH * H2 * W2 * FCH];

// ---------------- helpers ---------------------------------------------------
__device__ __forceinline__ unsigned smem_u32(const void* p) {
    return (unsigned)__cvta_generic_to_shared(p);
}
__device__ __forceinline__ void cp16p(unsigned dst, const void* src, bool p) {
    asm volatile("cp.async.cg.shared.global [%0], [%1], 16, %2;"
                 :: "r"(dst), "l"(src), "r"(p ? 16u : 0u));
}
#define CP_COMMIT() asm volatile("cp.async.commit_group;")
#define CP_WAIT0()  asm volatile("cp.async.wait_group 0;" ::: "memory")

__device__ __forceinline__ unsigned lds32(unsigned addr) {
    unsigned v;
    asm volatile("ld.shared.b32 %0, [%1];" : "=r"(v) : "r"(addr));
    return v;
}
__device__ __forceinline__ void mma_tf32(float c[4], const unsigned a[4],
                                         unsigned b0, unsigned b1) {
    asm volatile(
        "mma.sync.aligned.m16n8k8.row.col.f32.tf32.tf32.f32 "
        "{%0,%1,%2,%3}, {%4,%5,%6,%7}, {%8,%9}, {%0,%1,%2,%3};"
        : "+f"(c[0]), "+f"(c[1]), "+f"(c[2]), "+f"(c[3])
        : "r"(a[0]), "r"(a[1]), "r"(a[2]), "r"(a[3]), "r"(b0), "r"(b1));
}
__device__ __forceinline__ float to_tf32(float v) {
    unsigned u;
    asm("cvt.rna.tf32.f32 %0, %1;" : "=r"(u) : "f"(v));
    return __uint_as_float(u);
}
__device__ __forceinline__ float hsig(float z) {
    return fminf(fmaxf(0.2f * z + 0.5f, 0.f), 1.f);
}

// perm v2: cout = g*64+fc -> n = (fc>>3)*32 + g*8 + (fc&7)
__host__ __device__ __forceinline__ int perm_n(int cout) {
    int g = cout >> 6, fc = cout & 63;
    return (fc >> 3) * 32 + g * 8 + (fc & 7);
}

// step smem: A[0:46080) (180 rows x 256B, swizzled), B stages 2 x 32768
#define SB_BASE 46080
#define SB_STAGE 32768
#define ST_SMEM (SB_BASE + 2 * SB_STAGE)     // 111616
// ic smem: stage 32768 = A 16384 (128x128B) + B 16384; x2
#define IC_STAGE 32768
#define IC_SMEM 65536

// ---------------- prep kernels ---------------------------------------------
__global__ void prep_weights(const float* __restrict__ U,
                             const float* __restrict__ W,
                             const float* __restrict__ b) {
    int i = blockIdx.x * 256 + threadIdx.x;
    if (i < 9 * 64 * 256) {
        int tap = i / 16384, r = i % 16384, ci = r >> 8, cout = r & 255;
        g_ut[tap * 16384 + perm_n(cout) * 64 + ci] = to_tf32(U[i]);
    }
    if (i < 9 * 32 * 256) {
        int tap = i / 8192, r = i % 8192, ci = r >> 8, cout = r & 255;
        g_wt[tap * 8192 + perm_n(cout) * 32 + ci] = to_tf32(W[i]);
    }
    if (i < 256) g_bperm[perm_n(i)] = b[i];
}

__global__ void prep_x(const float* __restrict__ x) {
    size_t i = (size_t)blockIdx.x * 256 + threadIdx.x;
    g_xt[i] = to_tf32(x[i]);
}

// ---------------- input conv ------------------------------------------------
__device__ __forceinline__ void fill_ic(unsigned st, int tap, int img, int nh,
                                        int oh0, int ow0, int tid) {
    const int kh = tap / 3, kw = tap - kh * 3;
    // A im2col: 128 rows x 8 chunks of 16B (32 ch fp32), swizzled
    for (int i = tid; i < 1024; i += 256) {
        int row = i >> 3, cc = i & 7;
        int sr = row >> 4, sc = row & 15;
        int ih = 2 * (oh0 + sr) + kh, iw = 2 * (ow0 + sc) + kw;
        bool ok = (ih < 128 && iw < 128);
        const float* s = g_xt +
            (((size_t)img * 128 + (ok ? ih : 0)) * 128 + (ok ? iw : 0)) * 32 + cc * 4;
        cp16p(st + row * 128 + ((cc ^ (row & 7)) << 4), s, ok);
    }
    // B: 128 rows x 8 chunks
    for (int i = tid; i < 1024; i += 256) {
        int n = i >> 3, cc = i & 7;
        const float* s = g_wt + tap * 8192 + (nh * 128 + n) * 32 + cc * 4;
        cp16p(st + 16384 + n * 128 + ((cc ^ (n & 7)) << 4), s, true);
    }
    CP_COMMIT();
}

__global__ __launch_bounds__(256, 2) void ic_mma_kernel(float* __restrict__ xz)
{
    extern __shared__ __align__(1024) char smem[];
    unsigned sb = smem_u32(smem);
    const int tid = threadIdx.x, lane = tid & 31, wid = tid >> 5;
    const int mw = wid >> 2, nw = wid & 3;
    const int r = lane >> 2, cq = lane & 3;
    const int mt = blockIdx.x;
    const int img = blockIdx.y >> 1, nh = blockIdx.y & 1;
    const int oh0 = (mt >> 2) * 8, ow0 = (mt & 3) * 16;

    // frag base addresses (stage-relative)
    unsigned abase[4], nbase[4];
#pragma unroll
    for (int mf = 0; mf < 4; mf++)
        abase[mf] = (unsigned)((mw * 64 + mf * 16 + r) * 128 + cq * 4);
#pragma unroll
    for (int nf = 0; nf < 4; nf++)
        nbase[nf] = (unsigned)(16384 + (nw * 32 + nf * 8 + r) * 128 + cq * 4);

    float acc[4][4][4];
#pragma unroll
    for (int a = 0; a < 4; a++)
#pragma unroll
        for (int b = 0; b < 4; b++)
#pragma unroll
            for (int c = 0; c < 4; c++) acc[a][b][c] = 0.f;

    fill_ic(sb, 0, img, nh, oh0, ow0, tid);
    for (int tap = 0; tap < 9; tap++) {
        CP_WAIT0();
        __syncthreads();
        if (tap < 8)
            fill_ic(sb + ((tap + 1) & 1) * IC_STAGE, tap + 1, img, nh, oh0, ow0, tid);
        unsigned st = sb + (tap & 1) * IC_STAGE;
#pragma unroll
        for (int k = 0; k < 4; k++) {
            unsigned av[4][4], bv[4][2];
#pragma unroll
            for (int mf = 0; mf < 4; mf++) {
                unsigned o0 = (unsigned)(((2 * k) ^ r) << 4);   // row&7 == r
                unsigned base = st + abase[mf];
                av[mf][0] = lds32(base + o0);
                av[mf][1] = lds32(base + o0 + 1024);
                av[mf][2] = lds32(base + (o0 ^ 16));
                av[mf][3] = lds32(base + (o0 ^ 16) + 1024);
            }
#pragma unroll
            for (int nf = 0; nf < 4; nf++) {
                unsigned o0 = (unsigned)(((2 * k) ^ r) << 4);
                unsigned base = st + nbase[nf];
                bv[nf][0] = lds32(base + o0);
                bv[nf][1] = lds32(base + (o0 ^ 16));
            }
#pragma unroll
            for (int mf = 0; mf < 4; mf++)
#pragma unroll
                for (int nf = 0; nf < 4; nf++)
                    mma_tf32(acc[mf][nf], av[mf], bv[nf][0], bv[nf][1]);
        }
    }

    // epilogue: +bias(perm), write fragment blob
    float2 bvq[4];
#pragma unroll
    for (int nf = 0; nf < 4; nf++)
        bvq[nf] = *(const float2*)(g_bperm + nh * 128 + nw * 32 + nf * 8 + 2 * cq);
    float* blob = xz + ((((size_t)img * 32 + mt) * 2 + nh) * 8 + wid) * 2048 + lane;
#pragma unroll
    for (int mf = 0; mf < 4; mf++)
#pragma unroll
        for (int nf = 0; nf < 4; nf++)
#pragma unroll
            for (int rg = 0; rg < 4; rg++)
                blob[((mf * 4 + nf) * 4 + rg) * 32] =
                    acc[mf][nf][rg] + ((rg & 1) ? bvq[nf].y : bvq[nf].x);
}

// ---------------- LSTM step -------------------------------------------------
__device__ __forceinline__ void fill_b_step(unsigned dst, int tap, int nh, int tid) {
    const float* ut = g_ut + tap * 16384 + nh * 128 * 64;
    for (int i = tid; i < 2048; i += 256) {
        int n = i >> 4, cc = i & 15;
        cp16p(dst + n * 256 + ((cc ^ (n & 7)) << 4), ut + n * 64 + cc * 4, true);
    }
    CP_COMMIT();
}

__global__ __launch_bounds__(256, 2) void lstm_step_mma(
    const float* __restrict__ hin, float* __restrict__ hout,
    float* __restrict__ cbuf, const float* __restrict__ xz,
    const float* __restrict__ gamma, const float* __restrict__ beta,
    const float* __restrict__ mmean, const float* __restrict__ mvar,
    float* __restrict__ out, int t)
{
    extern __shared__ __align__(1024) char smem[];
    unsigned sb = smem_u32(smem);
    const int tid = threadIdx.x, lane = tid & 31, wid = tid >> 5;
    const int mw = wid >> 2, nw = wid & 3;
    const int r = lane >> 2, cq = lane & 3;
    const int mt = blockIdx.x;
    const int bb = blockIdx.y >> 1, nh = blockIdx.y & 1;
    const int oh0 = (mt >> 2) * 8, ow0 = (mt & 3) * 16;

    // A: halo'd h tile 10x18 spatial rows x 256B (64ch fp32), swizzled; once
    for (int i = tid; i < 2880; i += 256) {
        int row = i >> 4, cc = i & 15;
        int sr = row / 18, sc = row - sr * 18;
        int ih = oh0 - 1 + sr, iw = ow0 - 1 + sc;
        bool ok = (ih >= 0 && ih < H2 && iw >= 0 && iw < W2);
        const float* s = hin +
            (((size_t)bb * H2 + (ok ? ih : 0)) * W2 + (ok ? iw : 0)) * FCH + cc * 4;
        cp16p(sb + row * 256 + ((cc ^ (row & 7)) << 4), s, ok);
    }
    fill_b_step(sb + SB_BASE, 0, nh, tid);   // commits A + B0 together

    unsigned nbase[4];
#pragma unroll
    for (int nf = 0; nf < 4; nf++)
        nbase[nf] = (unsigned)((nw * 32 + nf * 8 + r) * 256 + cq * 4);

    float acc[4][4][4];
#pragma unroll
    for (int a = 0; a < 4; a++)
#pragma unroll
        for (int b = 0; b < 4; b++)
#pragma unroll
            for (int c = 0; c < 4; c++) acc[a][b][c] = 0.f;

    for (int tap = 0; tap < 9; tap++) {
        CP_WAIT0();
        __syncthreads();
        if (tap < 8)
            fill_b_step(sb + SB_BASE + ((tap + 1) & 1) * SB_STAGE, tap + 1, nh, tid);
        const int kh = tap / 3, kw = tap - kh * 3;
        unsigned Bst = sb + SB_BASE + (tap & 1) * SB_STAGE;

        unsigned abase[4];
        int ar7[4];
#pragma unroll
        for (int mf = 0; mf < 4; mf++) {
            int row0 = (mw * 4 + mf + kh) * 18 + r + kw;
            abase[mf] = sb + (unsigned)(row0 * 256 + cq * 4);
            ar7[mf] = row0 & 7;
        }

#pragma unroll
        for (int k = 0; k < 8; k++) {
            unsigned av[4][4], bv[4][2];
#pragma unroll
            for (int mf = 0; mf < 4; mf++) {
                unsigned o0 = (unsigned)(((2 * k) ^ ar7[mf]) << 4);
                av[mf][0] = lds32(abase[mf] + o0);
                av[mf][1] = lds32(abase[mf] + o0 + 2048);       // ow +8
                av[mf][2] = lds32(abase[mf] + (o0 ^ 16));
                av[mf][3] = lds32(abase[mf] + (o0 ^ 16) + 2048);
            }
            {
                unsigned o0 = (unsigned)(((2 * k) ^ r) << 4);   // n&7 == r
#pragma unroll
                for (int nf = 0; nf < 4; nf++) {
                    bv[nf][0] = lds32(Bst + nbase[nf] + o0);
                    bv[nf][1] = lds32(Bst + nbase[nf] + (o0 ^ 16));
                }
            }
#pragma unroll
            for (int mf = 0; mf < 4; mf++)
#pragma unroll
                for (int nf = 0; nf < 4; nf++)
                    mma_tf32(acc[mf][nf], av[mf], bv[nf][0], bv[nf][1]);
        }
    }

    // add xz (bias folded)
    const float* blob = xz +
        ((((size_t)(bb * TSTEPS + t) * 32 + mt) * 2 + nh) * 8 + wid) * 2048 + lane;
#pragma unroll
    for (int mf = 0; mf < 4; mf++)
#pragma unroll
        for (int nf = 0; nf < 4; nf++)
#pragma unroll
            for (int rg = 0; rg < 4; rg++)
                acc[mf][nf][rg] += blob[((mf * 4 + nf) * 4 + rg) * 32];

    // gates in-register: nf = gate; lane fc pair fc0, fc0+1
    const int fc0 = (nh * 4 + nw) * 8 + 2 * cq;
    float2 gm = *(const float2*)(gamma + fc0);
    float2 bt = *(const float2*)(beta + fc0);
    float2 mu = *(const float2*)(mmean + fc0);
    float2 vr = *(const float2*)(mvar + fc0);
    float sc0 = gm.x * rsqrtf(vr.x + 1e-3f);
    float sc1 = gm.y * rsqrtf(vr.y + 1e-3f);

#pragma unroll
    for (int mf = 0; mf < 4; mf++) {
        int oh = oh0 + mw * 4 + mf;
#pragma unroll
        for (int rh = 0; rh < 2; rh++) {
            int ow = ow0 + r + 8 * rh;
            size_t sidx = (((size_t)bb * H2 + oh) * W2 + ow) * FCH + fc0;
            float2 cc2 = *(const float2*)(cbuf + sidx);
            float cn[2], hn[2], ov[2];
#pragma unroll
            for (int q = 0; q < 2; q++) {
                float zi = acc[mf][0][2 * rh + q];
                float zf = acc[mf][1][2 * rh + q];
                float zg = acc[mf][2][2 * rh + q];
                float zo = acc[mf][3][2 * rh + q];
                float co = q ? cc2.y : cc2.x;
                float c2 = hsig(zf) * co + hsig(zi) * tanhf(zg);
                hn[q] = hsig(zo) * tanhf(c2);
                cn[q] = c2;
                float s = q ? sc1 : sc0;
                ov[q] = (hn[q] - (q ? mu.y : mu.x)) * s + (q ? bt.y : bt.x);
            }
            *(float2*)(cbuf + sidx) = make_float2(cn[0], cn[1]);
            *(float2*)(hout + sidx) = make_float2(to_tf32(hn[0]), to_tf32(hn[1]));
            *(float2*)(out + ((((size_t)bb * TSTEPS + t) * H2 + oh) * W2 + ow) * FCH + fc0)
                = make_float2(ov[0], ov[1]);
        }
    }
}

// ---------------------------------------------------------------------------
extern "C" void kernel_launch(void* const* d_in, const int* in_sizes, int n_in,
                              void* d_out, int out_size)
{
    const float* x     = (const float*)d_in[0];
    const float* W     = (const float*)d_in[1];
    const float* U     = (const float*)d_in[2];
    const float* b     = (const float*)d_in[3];
    const float* gamma = (const float*)d_in[4];
    const float* beta  = (const float*)d_in[5];
    const float* mm    = (const float*)d_in[6];
    const float* mv    = (const float*)d_in[7];
    float* out = (float*)d_out;

    float *xz, *cbuf, *hbuf;
    cudaGetSymbolAddress((void**)&xz, g_xz);
    cudaGetSymbolAddress((void**)&cbuf, g_c);
    cudaGetSymbolAddress((void**)&hbuf, g_ht);
    const size_t hsz = (size_t)BATCH * H2 * W2 * FCH;

    cudaFuncSetAttribute(ic_mma_kernel,
                         cudaFuncAttributeMaxDynamicSharedMemorySize, IC_SMEM);
    cudaFuncSetAttribute(lstm_step_mma,
                         cudaFuncAttributeMaxDynamicSharedMemorySize, ST_SMEM);

    cudaMemsetAsync(hbuf, 0, hsz * sizeof(float));
    cudaMemsetAsync(cbuf, 0, hsz * sizeof(float));

    prep_weights<<<576, 256>>>(U, W, b);
    prep_x<<<131072, 256>>>(x);
    ic_mma_kernel<<<dim3(32, 128), 256, IC_SMEM>>>(xz);

    for (int t = 0; t < TSTEPS; t++) {
        int rd = t & 1, wr = (t + 1) & 1;
        lstm_step_mma<<<dim3(32, 8), 256, ST_SMEM>>>(
            hbuf + rd * hsz, hbuf + wr * hsz,
            cbuf, xz, gamma, beta, mm, mv, out, t);
    }
}

// round 10
// speedup vs baseline: 9.6550x; 1.0676x over previous
#include <cuda_runtime.h>
#include <cuda_bf16.h>

// ---------------------------------------------------------------------------
// ConvLSTM via mma.sync tf32 single-pass, fp32 accum. Round 9 resubmit
// (broker flake). ic: x-tile staged once (raw fp32, in-register cvt.rna),
// B per-tap staged. step: unchanged from R8 (validated 38.2us).
// ---------------------------------------------------------------------------

#define H2 64
#define W2 64
#define FCH 64
#define BATCH 4
#define TSTEPS 16
#define NIMG 64

// xz blob: [img][mt32][nh2][warp8][frag64][lane32] floats
__device__ float g_xz[(size_t)NIMG * 32 * 2 * 8 * 64 * 32];          // 268 MB
__device__ float g_ut[9 * 256 * 64];     // [tap][n_perm][ci], tf32-rounded
__device__ float g_wt[9 * 256 * 32];     // [tap][n_perm][ci]
__device__ float g_bperm[256];
__device__ float g_ht[2][(size_t)BATCH * H2 * W2 * FCH];             // 2 x 4 MB
__device__ float g_c[(size_t)BATCH * H2 * W2 * FCH];

// ---------------- helpers ---------------------------------------------------
__device__ __forceinline__ unsigned smem_u32(const void* p) {
    return (unsigned)__cvta_generic_to_shared(p);
}
__device__ __forceinline__ void cp16p(unsigned dst, const void* src, bool p) {
    asm volatile("cp.async.cg.shared.global [%0], [%1], 16, %2;"
                 :: "r"(dst), "l"(src), "r"(p ? 16u : 0u));
}
#define CP_COMMIT() asm volatile("cp.async.commit_group;")
#define CP_WAIT0()  asm volatile("cp.async.wait_group 0;" ::: "memory")

__device__ __forceinline__ unsigned lds32(unsigned addr) {
    unsigned v;
    asm volatile("ld.shared.b32 %0, [%1];" : "=r"(v) : "r"(addr));
    return v;
}
__device__ __forceinline__ void mma_tf32(float c[4], const unsigned a[4],
                                         unsigned b0, unsigned b1) {
    asm volatile(
        "mma.sync.aligned.m16n8k8.row.col.f32.tf32.tf32.f32 "
        "{%0,%1,%2,%3}, {%4,%5,%6,%7}, {%8,%9}, {%0,%1,%2,%3};"
        : "+f"(c[0]), "+f"(c[1]), "+f"(c[2]), "+f"(c[3])
        : "r"(a[0]), "r"(a[1]), "r"(a[2]), "r"(a[3]), "r"(b0), "r"(b1));
}
__device__ __forceinline__ unsigned cvt_tf32u(unsigned v) {
    unsigned u;
    asm("cvt.rna.tf32.f32 %0, %1;" : "=r"(u) : "f"(__uint_as_float(v)));
    return u;
}
__device__ __forceinline__ float to_tf32(float v) {
    unsigned u;
    asm("cvt.rna.tf32.f32 %0, %1;" : "=r"(u) : "f"(v));
    return __uint_as_float(u);
}
__device__ __forceinline__ float hsig(float z) {
    return fminf(fmaxf(0.2f * z + 0.5f, 0.f), 1.f);
}

// perm v2: cout = g*64+fc -> n = (fc>>3)*32 + g*8 + (fc&7)
__host__ __device__ __forceinline__ int perm_n(int cout) {
    int g = cout >> 6, fc = cout & 63;
    return (fc >> 3) * 32 + g * 8 + (fc & 7);
}

// step smem: A[0:46080) (180 rows x 256B, swizzled), B stages 2 x 32768
#define SB_BASE 46080
#define SB_STAGE 32768
#define ST_SMEM (SB_BASE + 2 * SB_STAGE)     // 111616
// ic smem: A x-tile 561 rows x 128B = 71808; B stages 2 x 16384
#define ICB_BASE 71808
#define ICB_STAGE 16384
#define IC_SMEM (ICB_BASE + 2 * ICB_STAGE)   // 104576

// ---------------- prep --------------------------------------------------
__global__ void prep_weights(const float* __restrict__ U,
                             const float* __restrict__ W,
                             const float* __restrict__ b) {
    int i = blockIdx.x * 256 + threadIdx.x;
    if (i < 9 * 64 * 256) {
        int tap = i / 16384, r = i % 16384, ci = r >> 8, cout = r & 255;
        g_ut[tap * 16384 + perm_n(cout) * 64 + ci] = to_tf32(U[i]);
    }
    if (i < 9 * 32 * 256) {
        int tap = i / 8192, r = i % 8192, ci = r >> 8, cout = r & 255;
        g_wt[tap * 8192 + perm_n(cout) * 32 + ci] = to_tf32(W[i]);
    }
    if (i < 256) g_bperm[perm_n(i)] = b[i];
}

// ---------------- input conv ------------------------------------------------
// A: x-tile 17x33 spatial rows x 32ch fp32 (128B rows), swizzle key (row>>1)&7,
// staged ONCE. B: per-tap 128 n-rows x 32ch (128B rows), key row&7, 2 stages.
__device__ __forceinline__ void fill_icb(unsigned dst, int tap, int nh, int tid) {
    const float* wt = g_wt + tap * 8192 + nh * 128 * 32;
    for (int i = tid; i < 1024; i += 256) {
        int n = i >> 3, cc = i & 7;
        cp16p(dst + n * 128 + ((cc ^ (n & 7)) << 4), wt + n * 32 + cc * 4, true);
    }
    CP_COMMIT();
}

__global__ __launch_bounds__(256, 2) void ic_mma_kernel(
    const float* __restrict__ x, float* __restrict__ xz)
{
    extern __shared__ __align__(1024) char smem[];
    unsigned sb = smem_u32(smem);
    const int tid = threadIdx.x, lane = tid & 31, wid = tid >> 5;
    const int mw = wid >> 2, nw = wid & 3;
    const int r = lane >> 2, cq = lane & 3;
    const int mt = blockIdx.x;
    const int img = blockIdx.y >> 1, nh = blockIdx.y & 1;
    const int oh0 = (mt >> 2) * 8, ow0 = (mt & 3) * 16;
    const int ih0 = 2 * oh0, iw0 = 2 * ow0;

    // A fill: 561 tile-rows x 8 chunks, raw fp32 x, zero-fill OOB
    for (int i = tid; i < 4488; i += 256) {
        int row = i >> 3, cc = i & 7;
        int trow = row / 33, tcol = row - trow * 33;
        int ih = ih0 + trow, iw = iw0 + tcol;
        bool ok = (ih < 128 && iw < 128);
        const float* s = x +
            (((size_t)img * 128 + (ok ? ih : 0)) * 128 + (ok ? iw : 0)) * 32 + cc * 4;
        cp16p(sb + row * 128 + ((cc ^ ((row >> 1) & 7)) << 4), s, ok);
    }
    fill_icb(sb + ICB_BASE, 0, nh, tid);     // commits A + B0 together

    unsigned nbase[4];
#pragma unroll
    for (int nf = 0; nf < 4; nf++)
        nbase[nf] = (unsigned)((nw * 32 + nf * 8 + r) * 128 + cq * 4);

    float acc[4][4][4];
#pragma unroll
    for (int a = 0; a < 4; a++)
#pragma unroll
        for (int b = 0; b < 4; b++)
#pragma unroll
            for (int c = 0; c < 4; c++) acc[a][b][c] = 0.f;

    for (int tap = 0; tap < 9; tap++) {
        CP_WAIT0();
        __syncthreads();
        if (tap < 8)
            fill_icb(sb + ICB_BASE + ((tap + 1) & 1) * ICB_STAGE, tap + 1, nh, tid);
        const int kh = tap / 3, kw = tap - kh * 3;
        unsigned Bst = sb + ICB_BASE + (tap & 1) * ICB_STAGE;

        // per-mf A rows for this tap: sr = mw*4+mf, sc = r (+8 for av1/av3)
        unsigned abase[4];
        int akey[4];
#pragma unroll
        for (int mf = 0; mf < 4; mf++) {
            int row0 = (2 * (mw * 4 + mf) + kh) * 33 + (2 * r + kw);
            abase[mf] = sb + (unsigned)(row0 * 128 + cq * 4);
            akey[mf] = (row0 >> 1) & 7;      // same key for row0+16
        }

#pragma unroll
        for (int k = 0; k < 4; k++) {
            unsigned av[4][4], bv[4][2];
#pragma unroll
            for (int mf = 0; mf < 4; mf++) {
                unsigned o0 = (unsigned)(((2 * k) ^ akey[mf]) << 4);
                av[mf][0] = cvt_tf32u(lds32(abase[mf] + o0));
                av[mf][1] = cvt_tf32u(lds32(abase[mf] + o0 + 2048));  // sc +8
                av[mf][2] = cvt_tf32u(lds32(abase[mf] + (o0 ^ 16)));
                av[mf][3] = cvt_tf32u(lds32(abase[mf] + (o0 ^ 16) + 2048));
            }
            {
                unsigned o0 = (unsigned)(((2 * k) ^ r) << 4);   // B row&7 == r
#pragma unroll
                for (int nf = 0; nf < 4; nf++) {
                    bv[nf][0] = lds32(Bst + nbase[nf] + o0);
                    bv[nf][1] = lds32(Bst + nbase[nf] + (o0 ^ 16));
                }
            }
#pragma unroll
            for (int mf = 0; mf < 4; mf++)
#pragma unroll
                for (int nf = 0; nf < 4; nf++)
                    mma_tf32(acc[mf][nf], av[mf], bv[nf][0], bv[nf][1]);
        }
    }

    // epilogue: +bias(perm), write fragment blob
    float2 bvq[4];
#pragma unroll
    for (int nf = 0; nf < 4; nf++)
        bvq[nf] = *(const float2*)(g_bperm + nh * 128 + nw * 32 + nf * 8 + 2 * cq);
    float* blob = xz + ((((size_t)img * 32 + mt) * 2 + nh) * 8 + wid) * 2048 + lane;
#pragma unroll
    for (int mf = 0; mf < 4; mf++)
#pragma unroll
        for (int nf = 0; nf < 4; nf++)
#pragma unroll
            for (int rg = 0; rg < 4; rg++)
                blob[((mf * 4 + nf) * 4 + rg) * 32] =
                    acc[mf][nf][rg] + ((rg & 1) ? bvq[nf].y : bvq[nf].x);
}

// ---------------- LSTM step (unchanged from R8) ------------------------------
__device__ __forceinline__ void fill_b_step(unsigned dst, int tap, int nh, int tid) {
    const float* ut = g_ut + tap * 16384 + nh * 128 * 64;
    for (int i = tid; i < 2048; i += 256) {
        int n = i >> 4, cc = i & 15;
        cp16p(dst + n * 256 + ((cc ^ (n & 7)) << 4), ut + n * 64 + cc * 4, true);
    }
    CP_COMMIT();
}

__global__ __launch_bounds__(256, 2) void lstm_step_mma(
    const float* __restrict__ hin, float* __restrict__ hout,
    float* __restrict__ cbuf, const float* __restrict__ xz,
    const float* __restrict__ gamma, const float* __restrict__ beta,
    const float* __restrict__ mmean, const float* __restrict__ mvar,
    float* __restrict__ out, int t)
{
    extern __shared__ __align__(1024) char smem[];
    unsigned sb = smem_u32(smem);
    const int tid = threadIdx.x, lane = tid & 31, wid = tid >> 5;
    const int mw = wid >> 2, nw = wid & 3;
    const int r = lane >> 2, cq = lane & 3;
    const int mt = blockIdx.x;
    const int bb = blockIdx.y >> 1, nh = blockIdx.y & 1;
    const int oh0 = (mt >> 2) * 8, ow0 = (mt & 3) * 16;

    // A: halo'd h tile 10x18 spatial rows x 256B (64ch fp32), swizzled; once
    for (int i = tid; i < 2880; i += 256) {
        int row = i >> 4, cc = i & 15;
        int sr = row / 18, sc = row - sr * 18;
        int ih = oh0 - 1 + sr, iw = ow0 - 1 + sc;
        bool ok = (ih >= 0 && ih < H2 && iw >= 0 && iw < W2);
        const float* s = hin +
            (((size_t)bb * H2 + (ok ? ih : 0)) * W2 + (ok ? iw : 0)) * FCH + cc * 4;
        cp16p(sb + row * 256 + ((cc ^ (row & 7)) << 4), s, ok);
    }
    fill_b_step(sb + SB_BASE, 0, nh, tid);   // commits A + B0 together

    unsigned nbase[4];
#pragma unroll
    for (int nf = 0; nf < 4; nf++)
        nbase[nf] = (unsigned)((nw * 32 + nf * 8 + r) * 256 + cq * 4);

    float acc[4][4][4];
#pragma unroll
    for (int a = 0; a < 4; a++)
#pragma unroll
        for (int b = 0; b < 4; b++)
#pragma unroll
            for (int c = 0; c < 4; c++) acc[a][b][c] = 0.f;

    for (int tap = 0; tap < 9; tap++) {
        CP_WAIT0();
        __syncthreads();
        if (tap < 8)
            fill_b_step(sb + SB_BASE + ((tap + 1) & 1) * SB_STAGE, tap + 1, nh, tid);
        const int kh = tap / 3, kw = tap - kh * 3;
        unsigned Bst = sb + SB_BASE + (tap & 1) * SB_STAGE;

        unsigned abase[4];
        int ar7[4];
#pragma unroll
        for (int mf = 0; mf < 4; mf++) {
            int row0 = (mw * 4 + mf + kh) * 18 + r + kw;
            abase[mf] = sb + (unsigned)(row0 * 256 + cq * 4);
            ar7[mf] = row0 & 7;
        }

#pragma unroll
        for (int k = 0; k < 8; k++) {
            unsigned av[4][4], bv[4][2];
#pragma unroll
            for (int mf = 0; mf < 4; mf++) {
                unsigned o0 = (unsigned)(((2 * k) ^ ar7[mf]) << 4);
                av[mf][0] = lds32(abase[mf] + o0);
                av[mf][1] = lds32(abase[mf] + o0 + 2048);       // ow +8
                av[mf][2] = lds32(abase[mf] + (o0 ^ 16));
                av[mf][3] = lds32(abase[mf] + (o0 ^ 16) + 2048);
            }
            {
                unsigned o0 = (unsigned)(((2 * k) ^ r) << 4);   // n&7 == r
#pragma unroll
                for (int nf = 0; nf < 4; nf++) {
                    bv[nf][0] = lds32(Bst + nbase[nf] + o0);
                    bv[nf][1] = lds32(Bst + nbase[nf] + (o0 ^ 16));
                }
            }
#pragma unroll
            for (int mf = 0; mf < 4; mf++)
#pragma unroll
                for (int nf = 0; nf < 4; nf++)
                    mma_tf32(acc[mf][nf], av[mf], bv[nf][0], bv[nf][1]);
        }
    }

    // add xz (bias folded)
    const float* blob = xz +
        ((((size_t)(bb * TSTEPS + t) * 32 + mt) * 2 + nh) * 8 + wid) * 2048 + lane;
#pragma unroll
    for (int mf = 0; mf < 4; mf++)
#pragma unroll
        for (int nf = 0; nf < 4; nf++)
#pragma unroll
            for (int rg = 0; rg < 4; rg++)
                acc[mf][nf][rg] += blob[((mf * 4 + nf) * 4 + rg) * 32];

    // gates in-register: nf = gate; lane fc pair fc0, fc0+1
    const int fc0 = (nh * 4 + nw) * 8 + 2 * cq;
    float2 gm = *(const float2*)(gamma + fc0);
    float2 bt = *(const float2*)(beta + fc0);
    float2 mu = *(const float2*)(mmean + fc0);
    float2 vr = *(const float2*)(mvar + fc0);
    float sc0 = gm.x * rsqrtf(vr.x + 1e-3f);
    float sc1 = gm.y * rsqrtf(vr.y + 1e-3f);

#pragma unroll
    for (int mf = 0; mf < 4; mf++) {
        int oh = oh0 + mw * 4 + mf;
#pragma unroll
        for (int rh = 0; rh < 2; rh++) {
            int ow = ow0 + r + 8 * rh;
            size_t sidx = (((size_t)bb * H2 + oh) * W2 + ow) * FCH + fc0;
            float2 cc2 = *(const float2*)(cbuf + sidx);
            float cn[2], hn[2], ov[2];
#pragma unroll
            for (int q = 0; q < 2; q++) {
                float zi = acc[mf][0][2 * rh + q];
                float zf = acc[mf][1][2 * rh + q];
                float zg = acc[mf][2][2 * rh + q];
                float zo = acc[mf][3][2 * rh + q];
                float co = q ? cc2.y : cc2.x;
                float c2 = hsig(zf) * co + hsig(zi) * tanhf(zg);
                hn[q] = hsig(zo) * tanhf(c2);
                cn[q] = c2;
                float s = q ? sc1 : sc0;
                ov[q] = (hn[q] - (q ? mu.y : mu.x)) * s + (q ? bt.y : bt.x);
            }
            *(float2*)(cbuf + sidx) = make_float2(cn[0], cn[1]);
            *(float2*)(hout + sidx) = make_float2(to_tf32(hn[0]), to_tf32(hn[1]));
            *(float2*)(out + ((((size_t)bb * TSTEPS + t) * H2 + oh) * W2 + ow) * FCH + fc0)
                = make_float2(ov[0], ov[1]);
        }
    }
}

// ---------------------------------------------------------------------------
extern "C" void kernel_launch(void* const* d_in, const int* in_sizes, int n_in,
                              void* d_out, int out_size)
{
    const float* x     = (const float*)d_in[0];
    const float* W     = (const float*)d_in[1];
    const float* U     = (const float*)d_in[2];
    const float* b     = (const float*)d_in[3];
    const float* gamma = (const float*)d_in[4];
    const float* beta  = (const float*)d_in[5];
    const float* mm    = (const float*)d_in[6];
    const float* mv    = (const float*)d_in[7];
    float* out = (float*)d_out;

    float *xz, *cbuf, *hbuf;
    cudaGetSymbolAddress((void**)&xz, g_xz);
    cudaGetSymbolAddress((void**)&cbuf, g_c);
    cudaGetSymbolAddress((void**)&hbuf, g_ht);
    const size_t hsz = (size_t)BATCH * H2 * W2 * FCH;

    cudaFuncSetAttribute(ic_mma_kernel,
                         cudaFuncAttributeMaxDynamicSharedMemorySize, IC_SMEM);
    cudaFuncSetAttribute(lstm_step_mma,
                         cudaFuncAttributeMaxDynamicSharedMemorySize, ST_SMEM);

    cudaMemsetAsync(hbuf, 0, hsz * sizeof(float));
    cudaMemsetAsync(cbuf, 0, hsz * sizeof(float));

    prep_weights<<<576, 256>>>(U, W, b);
    ic_mma_kernel<<<dim3(32, 128), 256, IC_SMEM>>>(x, xz);

    for (int t = 0; t < TSTEPS; t++) {
        int rd = t & 1, wr = (t + 1) & 1;
        lstm_step_mma<<<dim3(32, 8), 256, ST_SMEM>>>(
            hbuf + rd * hsz, hbuf + wr * hsz,
            cbuf, xz, gamma, beta, mm, mv, out, t);
    }
}